// round 12
// baseline (speedup 1.0000x reference)
#include <cuda_runtime.h>
#include <cuda_bf16.h>
#include <math.h>
#include <stdint.h>

#define Bb 2
#define Ss 4096
#define Dd 512
#define NROWS (Bb*Ss)      // 8192
#define NEGF -1000000000.0f

// ---------------- scratch (device globals: allocation-free) ----------------
__device__ float g_h[NROWS*Dd];
#define SLOT_F 4224
__device__ float g_part[512 * SLOT_F];
__device__ __align__(16) __nv_bfloat16 g_xb[NROWS*Dd];    // x bf16, later ctx bf16
__device__ __align__(16) __nv_bfloat16 g_wtb[4*Dd*Dd];    // W^T bf16 x4
__device__ __align__(16) __nv_bfloat16 g_qc[16ULL*4096*64];
__device__ __align__(16) __nv_bfloat16 g_kc[16ULL*4096*64];
__device__ __align__(16) __nv_bfloat16 g_vc[16ULL*4096*64];

// ---------------- PTX helpers ----------------
__device__ __forceinline__ uint32_t smem_u32(const void* p) {
    return (uint32_t)__cvta_generic_to_shared(p);
}
#define CPASYNC16(dst, src) \
    asm volatile("cp.async.cg.shared.global [%0], [%1], 16;" :: "r"(dst), "l"(src))
#define CPCOMMIT() asm volatile("cp.async.commit_group;" ::: "memory")
#define CPWAIT(n)  asm volatile("cp.async.wait_group %0;" :: "n"(n) : "memory")

#define LDSM_X4(r0, r1, r2, r3, a) \
    asm volatile("ldmatrix.sync.aligned.m8n8.x4.shared.b16 {%0,%1,%2,%3}, [%4];" \
                 : "=r"(r0), "=r"(r1), "=r"(r2), "=r"(r3) : "r"(a))
#define LDSM_X4T(r0, r1, r2, r3, a) \
    asm volatile("ldmatrix.sync.aligned.m8n8.x4.trans.shared.b16 {%0,%1,%2,%3}, [%4];" \
                 : "=r"(r0), "=r"(r1), "=r"(r2), "=r"(r3) : "r"(a))

#define MMA16816(D, A, B0, B1) \
    asm volatile("mma.sync.aligned.m16n8k16.row.col.f32.bf16.bf16.f32 " \
                 "{%0,%1,%2,%3},{%4,%5,%6,%7},{%8,%9},{%0,%1,%2,%3};" \
                 : "+f"((D)[0]), "+f"((D)[1]), "+f"((D)[2]), "+f"((D)[3]) \
                 : "r"((A)[0]), "r"((A)[1]), "r"((A)[2]), "r"((A)[3]), \
                   "r"(B0), "r"(B1))

__device__ __forceinline__ uint32_t pack_hi(float a, float b) {
    __nv_bfloat162 h = __floats2bfloat162_rn(a, b);
    return *(uint32_t*)&h;
}

// ---------------------------------------------------------------------------
// Fused prep: x -> bf16 (CTAs 0..4095) and 4x W -> W^T bf16 (CTAs 4096..5119)
// ---------------------------------------------------------------------------
__global__ __launch_bounds__(256) void prep_kernel(
    const float* __restrict__ X, __nv_bfloat16* __restrict__ Xb,
    const float* __restrict__ W0, const float* __restrict__ W1,
    const float* __restrict__ W2, const float* __restrict__ W3,
    __nv_bfloat16* __restrict__ Th)
{
    int cb = blockIdx.x;
    int t = threadIdx.x;
    if (cb < 4096) {
        size_t i0 = (size_t)cb * 1024 + t * 2;
        float2 v0 = *(const float2*)&X[i0];
        float2 v1 = *(const float2*)&X[i0 + 512];
        *(uint32_t*)&Xb[i0]       = pack_hi(v0.x, v0.y);
        *(uint32_t*)&Xb[i0 + 512] = pack_hi(v1.x, v1.y);
        return;
    }
    __shared__ float tile[32][33];
    int idx = cb - 4096;
    int z = idx >> 8;
    int rest = idx & 255;
    const float* W = (z == 0) ? W0 : (z == 1) ? W1 : (z == 2) ? W2 : W3;
    __nv_bfloat16* th = Th + (size_t)z * 262144;
    int n0 = (rest & 15) * 32, k0 = (rest >> 4) * 32;
    int tx = t & 31, ty = t >> 5;
#pragma unroll
    for (int j = 0; j < 32; j += 8)
        tile[ty + j][tx] = W[(size_t)(k0 + ty + j) * 512 + n0 + tx];
    __syncthreads();
#pragma unroll
    for (int j = 0; j < 32; j += 8) {
        int row = ty + j;
        th[(size_t)(n0 + row) * 512 + k0 + tx] = __float2bfloat16(tile[tx][row]);
    }
}

// ---------------------------------------------------------------------------
// Single-term GEMM mainloop (CTA 128x128, BK=64, K=512 -> 8 chunks, dbl buf)
// ---------------------------------------------------------------------------
#define GEMM_SMEM 65536

__device__ __forceinline__ void gemm_ld_chunk(const __nv_bfloat16* __restrict__ A,
                                              const __nv_bfloat16* __restrict__ Bt,
                                              int rowBase, int colBase, int k0,
                                              uint32_t Ab, uint32_t Bbuf, int t)
{
#pragma unroll
    for (int it = 0; it < 4; it++) {
        int idx = it * 256 + t;
        int r = idx >> 3, c = idx & 7;
        uint32_t d = Ab + r * 128 + ((c ^ (r & 7)) << 4);
        CPASYNC16(d, &A[(size_t)(rowBase + r) * 512 + k0 + c * 8]);
    }
#pragma unroll
    for (int it = 0; it < 4; it++) {
        int idx = it * 256 + t;
        int r = idx >> 3, c = idx & 7;
        uint32_t d = Bbuf + r * 128 + ((c ^ (r & 7)) << 4);
        CPASYNC16(d, &Bt[(size_t)(colBase + r) * 512 + k0 + c * 8]);
    }
    CPCOMMIT();
}

__device__ __forceinline__ void gemm1_mainloop(const __nv_bfloat16* A, const __nv_bfloat16* Bt,
                                               int rowBase, int colBase, uint32_t sbase, int t,
                                               float acc[2][8][4])
{
    int w = t >> 5, lane = t & 31;
    int wm = (w & 3) * 32, wn = (w >> 2) * 64;
    int laneA_row = (((lane >> 3) & 1) << 3) + (lane & 7);
    int laneA_ch  = (lane >> 4);
    int laneB_row = ((lane >> 4) << 3) + (lane & 7);
    int laneB_ch  = ((lane >> 3) & 1);

    gemm_ld_chunk(A, Bt, rowBase, colBase, 0, sbase, sbase + 16384u, t);

    for (int i = 0; i < 8; i++) {
        int buf = i & 1;
        if (i < 7) {
            uint32_t Ab = sbase + (buf ? 0u : 32768u);
            gemm_ld_chunk(A, Bt, rowBase, colBase, (i + 1) * 64, Ab, Ab + 16384u, t);
            CPWAIT(1);
        } else {
            CPWAIT(0);
        }
        __syncthreads();

        uint32_t Ab = sbase + (buf ? 32768u : 0u);
        uint32_t Bbuf = Ab + 16384u;
#pragma unroll
        for (int ks = 0; ks < 4; ks++) {
            uint32_t afr[2][4];
#pragma unroll
            for (int mt = 0; mt < 2; mt++) {
                int row = wm + mt * 16 + laneA_row;
                int ch  = ks * 2 + laneA_ch;
                uint32_t a = Ab + row * 128 + ((ch ^ (row & 7)) << 4);
                LDSM_X4(afr[mt][0], afr[mt][1], afr[mt][2], afr[mt][3], a);
            }
#pragma unroll
            for (int p = 0; p < 4; p++) {
                int row = wn + p * 16 + laneB_row;
                int ch  = ks * 2 + laneB_ch;
                uint32_t a = Bbuf + row * 128 + ((ch ^ (row & 7)) << 4);
                uint32_t b0, b1, b2, b3;
                LDSM_X4(b0, b1, b2, b3, a);
#pragma unroll
                for (int mt = 0; mt < 2; mt++) {
                    MMA16816(acc[mt][p*2],   afr[mt], b0, b1);
                    MMA16816(acc[mt][p*2+1], afr[mt], b2, b3);
                }
            }
        }
        __syncthreads();
    }
}

// Wo GEMM
__global__ __launch_bounds__(256, 2)
void gemm_wo(const __nv_bfloat16* __restrict__ A,
             const __nv_bfloat16* __restrict__ Bt,
             float* __restrict__ Y)
{
    extern __shared__ __align__(128) char sm[];
    uint32_t sbase = smem_u32(sm);
    int t = threadIdx.x, w = t >> 5, lane = t & 31;
    int rowBase = blockIdx.y * 128, colBase = blockIdx.x * 128;
    int wm = (w & 3) * 32, wn = (w >> 2) * 64;

    float acc[2][8][4];
#pragma unroll
    for (int mt = 0; mt < 2; mt++)
#pragma unroll
        for (int nt = 0; nt < 8; nt++)
#pragma unroll
            for (int e = 0; e < 4; e++) acc[mt][nt][e] = 0.f;

    gemm1_mainloop(A, Bt, rowBase, colBase, sbase, t, acc);

#pragma unroll
    for (int mt = 0; mt < 2; mt++)
#pragma unroll
        for (int nt = 0; nt < 8; nt++) {
            float* a4 = acc[mt][nt];
            int r0 = rowBase + wm + mt * 16 + (lane >> 2);
            int c0 = colBase + wn + nt * 8 + (lane & 3) * 2;
            *(float2*)&Y[(size_t)r0 * 512 + c0] = make_float2(a4[0], a4[1]);
            *(float2*)&Y[(size_t)(r0+8) * 512 + c0] = make_float2(a4[2], a4[3]);
        }
}

// QKV GEMM -> per-head bf16 [bh][s][64]
__global__ __launch_bounds__(256, 2)
void gemm_qkv(const __nv_bfloat16* __restrict__ A,
              const __nv_bfloat16* __restrict__ Bt)
{
    extern __shared__ __align__(128) char sm[];
    uint32_t sbase = smem_u32(sm);
    int t = threadIdx.x, w = t >> 5, lane = t & 31;
    int rowBase = blockIdx.y * 128, colBase = blockIdx.x * 128;
    int wm = (w & 3) * 32, wn = (w >> 2) * 64;

    float acc[2][8][4];
#pragma unroll
    for (int mt = 0; mt < 2; mt++)
#pragma unroll
        for (int nt = 0; nt < 8; nt++)
#pragma unroll
            for (int e = 0; e < 4; e++) acc[mt][nt][e] = 0.f;

    gemm1_mainloop(A, Bt, rowBase, colBase, sbase, t, acc);

    int tensor = colBase >> 9;
    float alpha = (tensor == 0) ? 0.125f : 1.0f;
    __nv_bfloat16* dst = (tensor == 0) ? g_qc : (tensor == 1) ? g_kc : g_vc;

#pragma unroll
    for (int mt = 0; mt < 2; mt++)
#pragma unroll
        for (int nt = 0; nt < 8; nt++) {
            float* a4 = acc[mt][nt];
            int r0 = rowBase + wm + mt * 16 + (lane >> 2);
            int cc = (colBase & 511) + wn + nt * 8 + (lane & 3) * 2;
            int hh = cc >> 6, dd = cc & 63;
            int b = r0 >> 12, s = r0 & 4095;
            size_t off = ((size_t)((b << 3) + hh) * 4096 + s) * 64 + dd;
            *(uint32_t*)&dst[off] = pack_hi(a4[0]*alpha, a4[1]*alpha);
            *(uint32_t*)&dst[off + 8ULL*64] = pack_hi(a4[2]*alpha, a4[3]*alpha);
        }
}

// ---------------------------------------------------------------------------
// HMMA attention: 2-stage ring, 3 CTAs/SM target (regs capped via launch
// bounds; Q fragments reloaded from smem each iter to cut persistent regs).
// smem: QS 8K | KS0/1 16K | VS0/1 16K | EX 16.9K | km 512 | redL 512
// ---------------------------------------------------------------------------
#define OFF_KS 8192
#define OFF_VS 24576
#define OFF_EX 40960
#define EX_PITCH 66
#define OFF_KM 57856
#define OFF_RL 58368
#define ATT_SMEM 58880

__device__ __forceinline__ int kb_of(bool mid, int qb, int chunk, int itk,
                                     const int* __restrict__ rand_blocks)
{
    if (!mid) return chunk * 8 + itk;
    if (itk < 3) return qb - 1 + itk;
    if (itk == 3) return 0;
    if (itk == 4) return 63;
    return rand_blocks[(qb - 2) * 3 + (itk - 5)];
}

__device__ __forceinline__ void attn_prefetch_kv(int bh, int kb, uint32_t KSb,
                                                 uint32_t VSb, int t)
{
    size_t koff = ((size_t)bh * 4096 + kb * 64) * 64;
#pragma unroll
    for (int it = 0; it < 2; it++) {
        int idx = it * 256 + t;
        int r = idx >> 3, c = idx & 7;
        CPASYNC16(KSb + r * 128 + ((c ^ (r & 7)) << 4), &g_kc[koff + r * 64 + c * 8]);
    }
#pragma unroll
    for (int it = 0; it < 2; it++) {
        int idx = it * 256 + t;
        int r = idx >> 3, c = idx & 7;
        CPASYNC16(VSb + r * 128 + ((c ^ (r & 7)) << 4), &g_vc[koff + r * 64 + c * 8]);
    }
    CPCOMMIT();
}

__global__ __launch_bounds__(256, 3)
void attn_hmma(const float* __restrict__ mask, const int* __restrict__ rand_blocks)
{
    extern __shared__ __align__(128) char sm[];
    uint32_t sb = smem_u32(sm);
    const uint32_t QS = sb;
    float* km   = (float*)(sm + OFF_KM);    // [2][64]
    float* redL = (float*)(sm + OFF_RL);
    float* ex   = (float*)(sm + OFF_EX);    // [64][EX_PITCH]

    int t = threadIdx.x, w = t >> 5, lane = t & 31;
    int wm = (w & 3) * 16;
    int wni = w >> 2;
    int wn  = wni * 32;

    int u  = blockIdx.x % 92;
    int bh = blockIdx.x / 92;
    int b  = bh >> 3, h = bh & 7;

    bool mid = (u < 60);
    int qb, chunk = 0, di = 0;
    if (mid) { qb = u + 2; }
    else {
        int d = u - 60;
        di = d >> 3; chunk = d & 7;
        qb = (di < 2) ? di : (60 + di);
    }

    // ---- prologue: Q + K0/V0 via cp.async (one group), km[0] ----
    {
        size_t qoff = ((size_t)bh * 4096 + qb * 64) * 64;
#pragma unroll
        for (int it = 0; it < 2; it++) {
            int idx = it * 256 + t;
            int r = idx >> 3, c = idx & 7;
            CPASYNC16(QS + r * 128 + ((c ^ (r & 7)) << 4), &g_qc[qoff + r * 64 + c * 8]);
        }
        int kb0 = kb_of(mid, qb, chunk, 0, rand_blocks);
        attn_prefetch_kv(bh, kb0, sb + OFF_KS, sb + OFF_VS, t);
        if (t < 64) km[t] = mask[b * 4096 + kb0 * 64 + t];
    }

    int r1 = wm + (lane >> 2), r2 = r1 + 8;
    float mq1 = mask[b * 4096 + qb * 64 + r1];
    float mq2 = mask[b * 4096 + qb * 64 + r2];

    float acc[8][4];
#pragma unroll
    for (int nn = 0; nn < 8; nn++)
#pragma unroll
        for (int e = 0; e < 4; e++) acc[nn][e] = 0.f;
    float ls1 = 0.f, ls2 = 0.f;

    int laneA_row = (((lane >> 3) & 1) << 3) + (lane & 7);
    int laneA_ch  = lane >> 4;
    int laneB_row = ((lane >> 4) << 3) + (lane & 7);
    int laneB_ch  = (lane >> 3) & 1;
    int laneV_row = lane & 15;
    int laneV_g   = lane >> 4;

    for (int itk = 0; itk < 8; itk++) {
        int buf = itk & 1;
        bool band = mid && (itk < 3);

        __syncthreads();   // buf^1 tiles fully consumed (prev-prev iter)
        if (itk < 7) {
            int kbn = kb_of(mid, qb, chunk, itk + 1, rand_blocks);
            attn_prefetch_kv(bh, kbn, sb + OFF_KS + (buf ^ 1) * 8192,
                             sb + OFF_VS + (buf ^ 1) * 8192, t);
            if (t < 64) km[(buf ^ 1) * 64 + t] = mask[b * 4096 + kbn * 64 + t];
            CPWAIT(1);
        } else {
            CPWAIT(0);
        }
        __syncthreads();   // current buf visible

        uint32_t KSb = sb + OFF_KS + buf * 8192;
        uint32_t VSb = sb + OFF_VS + buf * 8192;
        const float* kmask_s = km + buf * 64;

        // ---- QK (Q fragments reloaded per iter to keep reg count low) ----
        float sc[4][4];
#pragma unroll
        for (int nt = 0; nt < 4; nt++)
#pragma unroll
            for (int e = 0; e < 4; e++) sc[nt][e] = 0.f;

#pragma unroll
        for (int ks = 0; ks < 4; ks++) {
            int kc2 = ks * 2;
            uint32_t qf[4];
            {
                int row = wm + laneA_row;
                int ch = kc2 + laneA_ch;
                LDSM_X4(qf[0], qf[1], qf[2], qf[3],
                        QS + row * 128 + ((ch ^ (row & 7)) << 4));
            }
#pragma unroll
            for (int g = 0; g < 2; g++) {
                uint32_t kh[4];
                int row = wn + g * 16 + laneB_row;
                int ch = kc2 + laneB_ch;
                LDSM_X4(kh[0], kh[1], kh[2], kh[3],
                        KSb + row * 128 + ((ch ^ (row & 7)) << 4));
                MMA16816(sc[g*2],   qf, kh[0], kh[1]);
                MMA16816(sc[g*2+1], qf, kh[2], kh[3]);
            }
        }

        // ---- mask ----
#pragma unroll
        for (int nt = 0; nt < 4; nt++) {
            int col = wn + nt * 8 + (lane & 3) * 2;
            float mk0 = kmask_s[col], mk1 = kmask_s[col + 1];
            float m00 = band ? mk0 * mq1 : mk0;
            float m01 = band ? mk1 * mq1 : mk1;
            float m10 = band ? mk0 * mq2 : mk0;
            float m11 = band ? mk1 * mq2 : mk1;
            sc[nt][0] += (1.0f - m00) * NEGF;
            sc[nt][1] += (1.0f - m01) * NEGF;
            sc[nt][2] += (1.0f - m10) * NEGF;
            sc[nt][3] += (1.0f - m11) * NEGF;
        }

        // ---- exp + bf16 pack ----
        uint32_t aph[2][4];
#pragma unroll
        for (int nt = 0; nt < 4; nt++) {
            float p00 = __expf(sc[nt][0]), p01 = __expf(sc[nt][1]);
            float p10 = __expf(sc[nt][2]), p11 = __expf(sc[nt][3]);
            ls1 += p00 + p01; ls2 += p10 + p11;
            int j = nt >> 1, hf = (nt & 1) * 2;
            aph[j][hf]     = pack_hi(p00, p01);
            aph[j][hf + 1] = pack_hi(p10, p11);
        }

        // ---- PV ----
#pragma unroll
        for (int j = 0; j < 2; j++) {
            int vrow = wn + j * 16 + laneV_row;
            uint32_t vbase = VSb + vrow * 128;
            int sw = (vrow & 7) << 4;
#pragma unroll
            for (int np = 0; np < 4; np++) {
                uint32_t vh4[4];
                int ch = np * 2 + laneV_g;
                LDSM_X4T(vh4[0], vh4[1], vh4[2], vh4[3], vbase + ((ch << 4) ^ sw));
                MMA16816(acc[np*2],   aph[j], vh4[0], vh4[1]);
                MMA16816(acc[np*2+1], aph[j], vh4[2], vh4[3]);
            }
        }
    }

    // ---- final ls combine ----
    ls1 += __shfl_xor_sync(0xffffffffu, ls1, 1);
    ls1 += __shfl_xor_sync(0xffffffffu, ls1, 2);
    ls2 += __shfl_xor_sync(0xffffffffu, ls2, 1);
    ls2 += __shfl_xor_sync(0xffffffffu, ls2, 2);
    if ((lane & 3) == 0) {
        redL[wni * 64 + r1] = ls1;
        redL[wni * 64 + r2] = ls2;
    }
    __syncthreads();
    ls1 = redL[r1] + redL[64 + r1];
    ls2 = redL[r2] + redL[64 + r2];

    // ---- cross-half acc reduction ----
    if (wni == 1) {
#pragma unroll
        for (int nn = 0; nn < 8; nn++) {
            int col = nn * 8 + (lane & 3) * 2;
            *(float2*)&ex[r1 * EX_PITCH + col] = make_float2(acc[nn][0], acc[nn][1]);
            *(float2*)&ex[r2 * EX_PITCH + col] = make_float2(acc[nn][2], acc[nn][3]);
        }
    }
    __syncthreads();
    if (wni == 0) {
#pragma unroll
        for (int nn = 0; nn < 8; nn++) {
            int col = nn * 8 + (lane & 3) * 2;
            float2 v1 = *(float2*)&ex[r1 * EX_PITCH + col];
            float2 v2 = *(float2*)&ex[r2 * EX_PITCH + col];
            acc[nn][0] += v1.x; acc[nn][1] += v1.y;
            acc[nn][2] += v2.x; acc[nn][3] += v2.y;
        }

        if (mid) {
            float inv1 = 1.0f / ls1, inv2 = 1.0f / ls2;
#pragma unroll
            for (int nn = 0; nn < 8; nn++) {
                int col = nn * 8 + (lane & 3) * 2;
                size_t o1 = ((size_t)(b * 4096 + qb * 64 + r1)) * 512 + h * 64 + col;
                size_t o2 = ((size_t)(b * 4096 + qb * 64 + r2)) * 512 + h * 64 + col;
                *(uint32_t*)&g_xb[o1] = pack_hi(acc[nn][0] * inv1, acc[nn][1] * inv1);
                *(uint32_t*)&g_xb[o2] = pack_hi(acc[nn][2] * inv2, acc[nn][3] * inv2);
            }
        } else {
            int slot = (bh * 4 + di) * 8 + chunk;
            float* p = g_part + (size_t)slot * SLOT_F;
#pragma unroll
            for (int nn = 0; nn < 8; nn++) {
                int col = nn * 8 + (lane & 3) * 2;
                *(float2*)&p[r1 * 64 + col] = make_float2(acc[nn][0], acc[nn][1]);
                *(float2*)&p[r2 * 64 + col] = make_float2(acc[nn][2], acc[nn][3]);
            }
            if ((lane & 3) == 0) {
                p[4096 + r1] = ls1;
                p[4096 + r2] = ls2;
            }
        }
    }
}

// ---------------------------------------------------------------------------
// Combine: 512 CTAs (64 groups x 8 col-slices), each thread 2 cols of 1 row.
// ---------------------------------------------------------------------------
__global__ __launch_bounds__(256) void combine_kernel()
{
    int blk = blockIdx.x;
    int g  = blk >> 3;
    int cs = (blk & 7) * 8;
    int bh = g >> 2, di = g & 3;
    int qb = (di < 2) ? di : (60 + di);
    int b  = bh >> 3, h = bh & 7;
    int t   = threadIdx.x;
    int row = t & 63;
    int c0  = cs + (t >> 6) * 2;

    const float* base = g_part + (size_t)(g * 8) * SLOT_F;
    float L = 0.f;
#pragma unroll
    for (int s = 0; s < 8; s++) L += base[s*SLOT_F + 4096 + row];
    float inv = 1.0f / L;

    float o0 = 0.f, o1 = 0.f;
#pragma unroll
    for (int s = 0; s < 8; s++) {
        float2 v = *(const float2*)&base[s*SLOT_F + row*64 + c0];
        o0 += v.x; o1 += v.y;
    }
    size_t dst = ((size_t)(b * 4096 + qb * 64 + row)) * 512 + h * 64 + c0;
    *(uint32_t*)&g_xb[dst] = pack_hi(o0 * inv, o1 * inv);
}

// ---------------------------------------------------------------------------
__global__ __launch_bounds__(256) void ln_kernel(const float* __restrict__ x,
                                                 const float* __restrict__ bo,
                                                 const float* __restrict__ gamma,
                                                 const float* __restrict__ beta,
                                                 float* __restrict__ out)
{
    int row = blockIdx.x;
    int t = threadIdx.x;
    size_t base = (size_t)row * 512;
    float h0 = g_h[base + t]       + bo[t]       + x[base + t];
    float h1 = g_h[base + t + 256] + bo[t + 256] + x[base + t + 256];
    float s = h0 + h1;
    float q = h0*h0 + h1*h1;
#pragma unroll
    for (int m = 16; m >= 1; m >>= 1) {
        s += __shfl_xor_sync(0xffffffffu, s, m);
        q += __shfl_xor_sync(0xffffffffu, q, m);
    }
    __shared__ float ss[8], qq[8];
    int w = t >> 5;
    if ((t & 31) == 0) { ss[w] = s; qq[w] = q; }
    __syncthreads();
    float S2 = 0.f, Q2 = 0.f;
#pragma unroll
    for (int i = 0; i < 8; i++) { S2 += ss[i]; Q2 += qq[i]; }
    float mu  = S2 * (1.0f / 512.0f);
    float var = Q2 * (1.0f / 512.0f) - mu * mu;
    float inv = rsqrtf(var + 1e-12f);
    out[base + t]       = (h0 - mu) * inv * gamma[t]       + beta[t];
    out[base + t + 256] = (h1 - mu) * inv * gamma[t + 256] + beta[t + 256];
}

// ---------------------------------------------------------------------------
extern "C" void kernel_launch(void* const* d_in, const int* in_sizes, int n_in,
                              void* d_out, int out_size)
{
    const float* x     = (const float*)d_in[0];
    const float* mask  = (const float*)d_in[1];
    const int*   rb    = (const int*)  d_in[2];
    const float* Wq    = (const float*)d_in[3];
    const float* Wk    = (const float*)d_in[4];
    const float* Wv    = (const float*)d_in[5];
    const float* Wo    = (const float*)d_in[6];
    const float* bo    = (const float*)d_in[7];
    const float* gamma = (const float*)d_in[8];
    const float* beta  = (const float*)d_in[9];
    float* out = (float*)d_out;

    float* hp;
    __nv_bfloat16 *xb, *wtb;
    cudaGetSymbolAddress((void**)&hp, g_h);
    cudaGetSymbolAddress((void**)&xb, g_xb);
    cudaGetSymbolAddress((void**)&wtb, g_wtb);

    cudaFuncSetAttribute(gemm_wo,  cudaFuncAttributeMaxDynamicSharedMemorySize, GEMM_SMEM);
    cudaFuncSetAttribute(gemm_qkv, cudaFuncAttributeMaxDynamicSharedMemorySize, GEMM_SMEM);
    cudaFuncSetAttribute(attn_hmma, cudaFuncAttributeMaxDynamicSharedMemorySize, ATT_SMEM);

    prep_kernel<<<4096 + 1024, 256>>>(x, xb, Wq, Wk, Wv, Wo, wtb);

    dim3 gq(12, 64);                         // 1536/128 x 8192/128
    gemm_qkv<<<gq, 256, GEMM_SMEM>>>(xb, wtb);

    attn_hmma<<<16 * 92, 256, ATT_SMEM>>>(mask, rb);
    combine_kernel<<<512, 256>>>();

    dim3 go(4, 64);
    gemm_wo<<<go, 256, GEMM_SMEM>>>(xb, wtb + 3*262144, hp);

    ln_kernel<<<Bb * Ss, 256>>>(x, bo, gamma, beta, out);
}

// round 13
// speedup vs baseline: 1.0172x; 1.0172x over previous
#include <cuda_runtime.h>
#include <cuda_bf16.h>
#include <math.h>
#include <stdint.h>

#define Bb 2
#define Ss 4096
#define Dd 512
#define NROWS (Bb*Ss)      // 8192
#define NEGF -1000000000.0f

// ---------------- scratch (device globals: allocation-free) ----------------
__device__ float g_h[NROWS*Dd];
#define SLOT_F 4224
__device__ float g_part[512 * SLOT_F];
__device__ __align__(16) __nv_bfloat16 g_xb[NROWS*Dd];    // x bf16, later ctx bf16
__device__ __align__(16) __nv_bfloat16 g_wtb[4*Dd*Dd];    // W^T bf16 x4
__device__ __align__(16) __nv_bfloat16 g_qc[16ULL*4096*64];
__device__ __align__(16) __nv_bfloat16 g_kc[16ULL*4096*64];
__device__ __align__(16) __nv_bfloat16 g_vc[16ULL*4096*64];

// ---------------- PTX helpers ----------------
__device__ __forceinline__ uint32_t smem_u32(const void* p) {
    return (uint32_t)__cvta_generic_to_shared(p);
}
#define CPASYNC16(dst, src) \
    asm volatile("cp.async.cg.shared.global [%0], [%1], 16;" :: "r"(dst), "l"(src))
#define CPCOMMIT() asm volatile("cp.async.commit_group;" ::: "memory")
#define CPWAIT(n)  asm volatile("cp.async.wait_group %0;" :: "n"(n) : "memory")

#define LDSM_X4(r0, r1, r2, r3, a) \
    asm volatile("ldmatrix.sync.aligned.m8n8.x4.shared.b16 {%0,%1,%2,%3}, [%4];" \
                 : "=r"(r0), "=r"(r1), "=r"(r2), "=r"(r3) : "r"(a))
#define LDSM_X4T(r0, r1, r2, r3, a) \
    asm volatile("ldmatrix.sync.aligned.m8n8.x4.trans.shared.b16 {%0,%1,%2,%3}, [%4];" \
                 : "=r"(r0), "=r"(r1), "=r"(r2), "=r"(r3) : "r"(a))

#define MMA16816(D, A, B0, B1) \
    asm volatile("mma.sync.aligned.m16n8k16.row.col.f32.bf16.bf16.f32 " \
                 "{%0,%1,%2,%3},{%4,%5,%6,%7},{%8,%9},{%0,%1,%2,%3};" \
                 : "+f"((D)[0]), "+f"((D)[1]), "+f"((D)[2]), "+f"((D)[3]) \
                 : "r"((A)[0]), "r"((A)[1]), "r"((A)[2]), "r"((A)[3]), \
                   "r"(B0), "r"(B1))

__device__ __forceinline__ uint32_t pack_hi(float a, float b) {
    __nv_bfloat162 h = __floats2bfloat162_rn(a, b);
    return *(uint32_t*)&h;
}

// ---------------------------------------------------------------------------
// Fused prep: x -> bf16 (CTAs 0..4095) and 4x W -> W^T bf16 (CTAs 4096..5119)
// ---------------------------------------------------------------------------
__global__ __launch_bounds__(256) void prep_kernel(
    const float* __restrict__ X, __nv_bfloat16* __restrict__ Xb,
    const float* __restrict__ W0, const float* __restrict__ W1,
    const float* __restrict__ W2, const float* __restrict__ W3,
    __nv_bfloat16* __restrict__ Th)
{
    int cb = blockIdx.x;
    int t = threadIdx.x;
    if (cb < 4096) {
        size_t i0 = (size_t)cb * 1024 + t * 2;
        float2 v0 = *(const float2*)&X[i0];
        float2 v1 = *(const float2*)&X[i0 + 512];
        *(uint32_t*)&Xb[i0]       = pack_hi(v0.x, v0.y);
        *(uint32_t*)&Xb[i0 + 512] = pack_hi(v1.x, v1.y);
        return;
    }
    __shared__ float tile[32][33];
    int idx = cb - 4096;
    int z = idx >> 8;
    int rest = idx & 255;
    const float* W = (z == 0) ? W0 : (z == 1) ? W1 : (z == 2) ? W2 : W3;
    __nv_bfloat16* th = Th + (size_t)z * 262144;
    int n0 = (rest & 15) * 32, k0 = (rest >> 4) * 32;
    int tx = t & 31, ty = t >> 5;
#pragma unroll
    for (int j = 0; j < 32; j += 8)
        tile[ty + j][tx] = W[(size_t)(k0 + ty + j) * 512 + n0 + tx];
    __syncthreads();
#pragma unroll
    for (int j = 0; j < 32; j += 8) {
        int row = ty + j;
        th[(size_t)(n0 + row) * 512 + k0 + tx] = __float2bfloat16(tile[tx][row]);
    }
}

// ---------------------------------------------------------------------------
// Single-term GEMM mainloop (CTA 128x128, BK=64, K=512 -> 8 chunks, dbl buf)
// ---------------------------------------------------------------------------
#define GEMM_SMEM 65536

__device__ __forceinline__ void gemm_ld_chunk(const __nv_bfloat16* __restrict__ A,
                                              const __nv_bfloat16* __restrict__ Bt,
                                              int rowBase, int colBase, int k0,
                                              uint32_t Ab, uint32_t Bbuf, int t)
{
#pragma unroll
    for (int it = 0; it < 4; it++) {
        int idx = it * 256 + t;
        int r = idx >> 3, c = idx & 7;
        uint32_t d = Ab + r * 128 + ((c ^ (r & 7)) << 4);
        CPASYNC16(d, &A[(size_t)(rowBase + r) * 512 + k0 + c * 8]);
    }
#pragma unroll
    for (int it = 0; it < 4; it++) {
        int idx = it * 256 + t;
        int r = idx >> 3, c = idx & 7;
        uint32_t d = Bbuf + r * 128 + ((c ^ (r & 7)) << 4);
        CPASYNC16(d, &Bt[(size_t)(colBase + r) * 512 + k0 + c * 8]);
    }
    CPCOMMIT();
}

__device__ __forceinline__ void gemm1_mainloop(const __nv_bfloat16* A, const __nv_bfloat16* Bt,
                                               int rowBase, int colBase, uint32_t sbase, int t,
                                               float acc[2][8][4])
{
    int w = t >> 5, lane = t & 31;
    int wm = (w & 3) * 32, wn = (w >> 2) * 64;
    int laneA_row = (((lane >> 3) & 1) << 3) + (lane & 7);
    int laneA_ch  = (lane >> 4);
    int laneB_row = ((lane >> 4) << 3) + (lane & 7);
    int laneB_ch  = ((lane >> 3) & 1);

    gemm_ld_chunk(A, Bt, rowBase, colBase, 0, sbase, sbase + 16384u, t);

    for (int i = 0; i < 8; i++) {
        int buf = i & 1;
        if (i < 7) {
            uint32_t Ab = sbase + (buf ? 0u : 32768u);
            gemm_ld_chunk(A, Bt, rowBase, colBase, (i + 1) * 64, Ab, Ab + 16384u, t);
            CPWAIT(1);
        } else {
            CPWAIT(0);
        }
        __syncthreads();

        uint32_t Ab = sbase + (buf ? 32768u : 0u);
        uint32_t Bbuf = Ab + 16384u;
#pragma unroll
        for (int ks = 0; ks < 4; ks++) {
            uint32_t afr[2][4];
#pragma unroll
            for (int mt = 0; mt < 2; mt++) {
                int row = wm + mt * 16 + laneA_row;
                int ch  = ks * 2 + laneA_ch;
                uint32_t a = Ab + row * 128 + ((ch ^ (row & 7)) << 4);
                LDSM_X4(afr[mt][0], afr[mt][1], afr[mt][2], afr[mt][3], a);
            }
#pragma unroll
            for (int p = 0; p < 4; p++) {
                int row = wn + p * 16 + laneB_row;
                int ch  = ks * 2 + laneB_ch;
                uint32_t a = Bbuf + row * 128 + ((ch ^ (row & 7)) << 4);
                uint32_t b0, b1, b2, b3;
                LDSM_X4(b0, b1, b2, b3, a);
#pragma unroll
                for (int mt = 0; mt < 2; mt++) {
                    MMA16816(acc[mt][p*2],   afr[mt], b0, b1);
                    MMA16816(acc[mt][p*2+1], afr[mt], b2, b3);
                }
            }
        }
        __syncthreads();
    }
}

// Wo GEMM
__global__ __launch_bounds__(256, 2)
void gemm_wo(const __nv_bfloat16* __restrict__ A,
             const __nv_bfloat16* __restrict__ Bt,
             float* __restrict__ Y)
{
    extern __shared__ __align__(128) char sm[];
    uint32_t sbase = smem_u32(sm);
    int t = threadIdx.x, w = t >> 5, lane = t & 31;
    int rowBase = blockIdx.y * 128, colBase = blockIdx.x * 128;
    int wm = (w & 3) * 32, wn = (w >> 2) * 64;

    float acc[2][8][4];
#pragma unroll
    for (int mt = 0; mt < 2; mt++)
#pragma unroll
        for (int nt = 0; nt < 8; nt++)
#pragma unroll
            for (int e = 0; e < 4; e++) acc[mt][nt][e] = 0.f;

    gemm1_mainloop(A, Bt, rowBase, colBase, sbase, t, acc);

#pragma unroll
    for (int mt = 0; mt < 2; mt++)
#pragma unroll
        for (int nt = 0; nt < 8; nt++) {
            float* a4 = acc[mt][nt];
            int r0 = rowBase + wm + mt * 16 + (lane >> 2);
            int c0 = colBase + wn + nt * 8 + (lane & 3) * 2;
            *(float2*)&Y[(size_t)r0 * 512 + c0] = make_float2(a4[0], a4[1]);
            *(float2*)&Y[(size_t)(r0+8) * 512 + c0] = make_float2(a4[2], a4[3]);
        }
}

// QKV GEMM -> per-head bf16 [bh][s][64]
__global__ __launch_bounds__(256, 2)
void gemm_qkv(const __nv_bfloat16* __restrict__ A,
              const __nv_bfloat16* __restrict__ Bt)
{
    extern __shared__ __align__(128) char sm[];
    uint32_t sbase = smem_u32(sm);
    int t = threadIdx.x, w = t >> 5, lane = t & 31;
    int rowBase = blockIdx.y * 128, colBase = blockIdx.x * 128;
    int wm = (w & 3) * 32, wn = (w >> 2) * 64;

    float acc[2][8][4];
#pragma unroll
    for (int mt = 0; mt < 2; mt++)
#pragma unroll
        for (int nt = 0; nt < 8; nt++)
#pragma unroll
            for (int e = 0; e < 4; e++) acc[mt][nt][e] = 0.f;

    gemm1_mainloop(A, Bt, rowBase, colBase, sbase, t, acc);

    int tensor = colBase >> 9;
    float alpha = (tensor == 0) ? 0.125f : 1.0f;
    __nv_bfloat16* dst = (tensor == 0) ? g_qc : (tensor == 1) ? g_kc : g_vc;

#pragma unroll
    for (int mt = 0; mt < 2; mt++)
#pragma unroll
        for (int nt = 0; nt < 8; nt++) {
            float* a4 = acc[mt][nt];
            int r0 = rowBase + wm + mt * 16 + (lane >> 2);
            int cc = (colBase & 511) + wn + nt * 8 + (lane & 3) * 2;
            int hh = cc >> 6, dd = cc & 63;
            int b = r0 >> 12, s = r0 & 4095;
            size_t off = ((size_t)((b << 3) + hh) * 4096 + s) * 64 + dd;
            *(uint32_t*)&dst[off] = pack_hi(a4[0]*alpha, a4[1]*alpha);
            *(uint32_t*)&dst[off + 8ULL*64] = pack_hi(a4[2]*alpha, a4[3]*alpha);
        }
}

// ---------------------------------------------------------------------------
// HMMA attention (best-known config = R10): 2-stage ring, hoisted Q, (256,2).
// smem: QS 8K | KS0/1 16K | VS0/1 16K | EX 16.9K | km 512 | redL 512
// ---------------------------------------------------------------------------
#define OFF_KS 8192
#define OFF_VS 24576
#define OFF_EX 40960
#define EX_PITCH 66
#define OFF_KM 57856
#define OFF_RL 58368
#define ATT_SMEM 58880

__device__ __forceinline__ int kb_of(bool mid, int qb, int chunk, int itk,
                                     const int* __restrict__ rand_blocks)
{
    if (!mid) return chunk * 8 + itk;
    if (itk < 3) return qb - 1 + itk;
    if (itk == 3) return 0;
    if (itk == 4) return 63;
    return rand_blocks[(qb - 2) * 3 + (itk - 5)];
}

__device__ __forceinline__ void attn_prefetch_kv(int bh, int kb, uint32_t KSb,
                                                 uint32_t VSb, int t)
{
    size_t koff = ((size_t)bh * 4096 + kb * 64) * 64;
#pragma unroll
    for (int it = 0; it < 2; it++) {
        int idx = it * 256 + t;
        int r = idx >> 3, c = idx & 7;
        CPASYNC16(KSb + r * 128 + ((c ^ (r & 7)) << 4), &g_kc[koff + r * 64 + c * 8]);
    }
#pragma unroll
    for (int it = 0; it < 2; it++) {
        int idx = it * 256 + t;
        int r = idx >> 3, c = idx & 7;
        CPASYNC16(VSb + r * 128 + ((c ^ (r & 7)) << 4), &g_vc[koff + r * 64 + c * 8]);
    }
    CPCOMMIT();
}

__global__ __launch_bounds__(256, 2)
void attn_hmma(const float* __restrict__ mask, const int* __restrict__ rand_blocks)
{
    extern __shared__ __align__(128) char sm[];
    uint32_t sb = smem_u32(sm);
    const uint32_t QS = sb;
    float* km   = (float*)(sm + OFF_KM);    // [2][64]
    float* redL = (float*)(sm + OFF_RL);
    float* ex   = (float*)(sm + OFF_EX);    // [64][EX_PITCH]

    int t = threadIdx.x, w = t >> 5, lane = t & 31;
    int wm = (w & 3) * 16;
    int wni = w >> 2;
    int wn  = wni * 32;

    int u  = blockIdx.x % 92;
    int bh = blockIdx.x / 92;
    int b  = bh >> 3, h = bh & 7;

    bool mid = (u < 60);
    int qb, chunk = 0, di = 0;
    if (mid) { qb = u + 2; }
    else {
        int d = u - 60;
        di = d >> 3; chunk = d & 7;
        qb = (di < 2) ? di : (60 + di);
    }

    // ---- prologue: Q + K0/V0 via cp.async (one group), km[0] ----
    {
        size_t qoff = ((size_t)bh * 4096 + qb * 64) * 64;
#pragma unroll
        for (int it = 0; it < 2; it++) {
            int idx = it * 256 + t;
            int r = idx >> 3, c = idx & 7;
            CPASYNC16(QS + r * 128 + ((c ^ (r & 7)) << 4), &g_qc[qoff + r * 64 + c * 8]);
        }
        int kb0 = kb_of(mid, qb, chunk, 0, rand_blocks);
        attn_prefetch_kv(bh, kb0, sb + OFF_KS, sb + OFF_VS, t);
        if (t < 64) km[t] = mask[b * 4096 + kb0 * 64 + t];
    }

    int r1 = wm + (lane >> 2), r2 = r1 + 8;
    float mq1 = mask[b * 4096 + qb * 64 + r1];
    float mq2 = mask[b * 4096 + qb * 64 + r2];

    float acc[8][4];
#pragma unroll
    for (int nn = 0; nn < 8; nn++)
#pragma unroll
        for (int e = 0; e < 4; e++) acc[nn][e] = 0.f;
    float ls1 = 0.f, ls2 = 0.f;

    int laneA_row = (((lane >> 3) & 1) << 3) + (lane & 7);
    int laneA_ch  = lane >> 4;
    int laneB_row = ((lane >> 4) << 3) + (lane & 7);
    int laneB_ch  = (lane >> 3) & 1;
    int laneV_row = lane & 15;
    int laneV_g   = lane >> 4;

    uint32_t qh[4][4];

    for (int itk = 0; itk < 8; itk++) {
        int buf = itk & 1;
        bool band = mid && (itk < 3);

        __syncthreads();
        if (itk < 7) {
            int kbn = kb_of(mid, qb, chunk, itk + 1, rand_blocks);
            attn_prefetch_kv(bh, kbn, sb + OFF_KS + (buf ^ 1) * 8192,
                             sb + OFF_VS + (buf ^ 1) * 8192, t);
            if (t < 64) km[(buf ^ 1) * 64 + t] = mask[b * 4096 + kbn * 64 + t];
            CPWAIT(1);
        } else {
            CPWAIT(0);
        }
        __syncthreads();

        if (itk == 0) {
            int row = wm + laneA_row;
#pragma unroll
            for (int ks = 0; ks < 4; ks++) {
                int ch = ks * 2 + laneA_ch;
                LDSM_X4(qh[ks][0], qh[ks][1], qh[ks][2], qh[ks][3],
                        QS + row * 128 + ((ch ^ (row & 7)) << 4));
            }
        }

        uint32_t KSb = sb + OFF_KS + buf * 8192;
        uint32_t VSb = sb + OFF_VS + buf * 8192;
        const float* kmask_s = km + buf * 64;

        // ---- QK ----
        float sc[4][4];
#pragma unroll
        for (int nt = 0; nt < 4; nt++)
#pragma unroll
            for (int e = 0; e < 4; e++) sc[nt][e] = 0.f;

#pragma unroll
        for (int ks = 0; ks < 4; ks++) {
            int kc2 = ks * 2;
#pragma unroll
            for (int g = 0; g < 2; g++) {
                uint32_t kh[4];
                int row = wn + g * 16 + laneB_row;
                int ch = kc2 + laneB_ch;
                LDSM_X4(kh[0], kh[1], kh[2], kh[3],
                        KSb + row * 128 + ((ch ^ (row & 7)) << 4));
                MMA16816(sc[g*2],   qh[ks], kh[0], kh[1]);
                MMA16816(sc[g*2+1], qh[ks], kh[2], kh[3]);
            }
        }

        // ---- mask ----
#pragma unroll
        for (int nt = 0; nt < 4; nt++) {
            int col = wn + nt * 8 + (lane & 3) * 2;
            float mk0 = kmask_s[col], mk1 = kmask_s[col + 1];
            float m00 = band ? mk0 * mq1 : mk0;
            float m01 = band ? mk1 * mq1 : mk1;
            float m10 = band ? mk0 * mq2 : mk0;
            float m11 = band ? mk1 * mq2 : mk1;
            sc[nt][0] += (1.0f - m00) * NEGF;
            sc[nt][1] += (1.0f - m01) * NEGF;
            sc[nt][2] += (1.0f - m10) * NEGF;
            sc[nt][3] += (1.0f - m11) * NEGF;
        }

        // ---- exp + bf16 pack ----
        uint32_t aph[2][4];
#pragma unroll
        for (int nt = 0; nt < 4; nt++) {
            float p00 = __expf(sc[nt][0]), p01 = __expf(sc[nt][1]);
            float p10 = __expf(sc[nt][2]), p11 = __expf(sc[nt][3]);
            ls1 += p00 + p01; ls2 += p10 + p11;
            int j = nt >> 1, hf = (nt & 1) * 2;
            aph[j][hf]     = pack_hi(p00, p01);
            aph[j][hf + 1] = pack_hi(p10, p11);
        }

        // ---- PV ----
#pragma unroll
        for (int j = 0; j < 2; j++) {
            int vrow = wn + j * 16 + laneV_row;
            uint32_t vbase = VSb + vrow * 128;
            int sw = (vrow & 7) << 4;
#pragma unroll
            for (int np = 0; np < 4; np++) {
                uint32_t vh4[4];
                int ch = np * 2 + laneV_g;
                LDSM_X4T(vh4[0], vh4[1], vh4[2], vh4[3], vbase + ((ch << 4) ^ sw));
                MMA16816(acc[np*2],   aph[j], vh4[0], vh4[1]);
                MMA16816(acc[np*2+1], aph[j], vh4[2], vh4[3]);
            }
        }
    }

    // ---- final ls combine ----
    ls1 += __shfl_xor_sync(0xffffffffu, ls1, 1);
    ls1 += __shfl_xor_sync(0xffffffffu, ls1, 2);
    ls2 += __shfl_xor_sync(0xffffffffu, ls2, 1);
    ls2 += __shfl_xor_sync(0xffffffffu, ls2, 2);
    if ((lane & 3) == 0) {
        redL[wni * 64 + r1] = ls1;
        redL[wni * 64 + r2] = ls2;
    }
    __syncthreads();
    ls1 = redL[r1] + redL[64 + r1];
    ls2 = redL[r2] + redL[64 + r2];

    // ---- cross-half acc reduction ----
    if (wni == 1) {
#pragma unroll
        for (int nn = 0; nn < 8; nn++) {
            int col = nn * 8 + (lane & 3) * 2;
            *(float2*)&ex[r1 * EX_PITCH + col] = make_float2(acc[nn][0], acc[nn][1]);
            *(float2*)&ex[r2 * EX_PITCH + col] = make_float2(acc[nn][2], acc[nn][3]);
        }
    }
    __syncthreads();
    if (wni == 0) {
#pragma unroll
        for (int nn = 0; nn < 8; nn++) {
            int col = nn * 8 + (lane & 3) * 2;
            float2 v1 = *(float2*)&ex[r1 * EX_PITCH + col];
            float2 v2 = *(float2*)&ex[r2 * EX_PITCH + col];
            acc[nn][0] += v1.x; acc[nn][1] += v1.y;
            acc[nn][2] += v2.x; acc[nn][3] += v2.y;
        }

        if (mid) {
            float inv1 = 1.0f / ls1, inv2 = 1.0f / ls2;
#pragma unroll
            for (int nn = 0; nn < 8; nn++) {
                int col = nn * 8 + (lane & 3) * 2;
                size_t o1 = ((size_t)(b * 4096 + qb * 64 + r1)) * 512 + h * 64 + col;
                size_t o2 = ((size_t)(b * 4096 + qb * 64 + r2)) * 512 + h * 64 + col;
                *(uint32_t*)&g_xb[o1] = pack_hi(acc[nn][0] * inv1, acc[nn][1] * inv1);
                *(uint32_t*)&g_xb[o2] = pack_hi(acc[nn][2] * inv2, acc[nn][3] * inv2);
            }
        } else {
            int slot = (bh * 4 + di) * 8 + chunk;
            float* p = g_part + (size_t)slot * SLOT_F;
#pragma unroll
            for (int nn = 0; nn < 8; nn++) {
                int col = nn * 8 + (lane & 3) * 2;
                *(float2*)&p[r1 * 64 + col] = make_float2(acc[nn][0], acc[nn][1]);
                *(float2*)&p[r2 * 64 + col] = make_float2(acc[nn][2], acc[nn][3]);
            }
            if ((lane & 3) == 0) {
                p[4096 + r1] = ls1;
                p[4096 + r2] = ls2;
            }
        }
    }
}

// ---------------------------------------------------------------------------
// Combine: one CTA per dense group; coalesced float4 sweeps over partials.
// ---------------------------------------------------------------------------
__global__ __launch_bounds__(256) void combine_kernel()
{
    __shared__ float sinv[64];
    int g  = blockIdx.x;
    int bh = g >> 2, di = g & 3;
    int qb = (di < 2) ? di : (60 + di);
    int b  = bh >> 3, h = bh & 7;
    int t  = threadIdx.x;

    const float* base = g_part + (size_t)(g * 8) * SLOT_F;
    if (t < 64) {
        float L = 0.f;
#pragma unroll
        for (int s = 0; s < 8; s++) L += base[s*SLOT_F + 4096 + t];
        sinv[t] = 1.0f / L;
    }
    __syncthreads();

    size_t rowBase = ((size_t)(b * 4096 + qb * 64)) * 512 + h * 64;
#pragma unroll
    for (int it = 0; it < 4; it++) {
        int idx4 = it * 256 + t;           // float4 index within 64x64 tile
        float4 o = make_float4(0.f, 0.f, 0.f, 0.f);
#pragma unroll
        for (int s = 0; s < 8; s++) {
            float4 v = *(const float4*)&base[s*SLOT_F + idx4 * 4];
            o.x += v.x; o.y += v.y; o.z += v.z; o.w += v.w;
        }
        int row = idx4 >> 4;
        int col = (idx4 & 15) * 4;
        float inv = sinv[row];
        uint32_t p0 = pack_hi(o.x * inv, o.y * inv);
        uint32_t p1 = pack_hi(o.z * inv, o.w * inv);
        uint2 pk = make_uint2(p0, p1);
        *(uint2*)&g_xb[rowBase + (size_t)row * 512 + col] = pk;
    }
}

// ---------------------------------------------------------------------------
__global__ __launch_bounds__(256) void ln_kernel(const float* __restrict__ x,
                                                 const float* __restrict__ bo,
                                                 const float* __restrict__ gamma,
                                                 const float* __restrict__ beta,
                                                 float* __restrict__ out)
{
    int row = blockIdx.x;
    int t = threadIdx.x;
    size_t base = (size_t)row * 512;
    float h0 = g_h[base + t]       + bo[t]       + x[base + t];
    float h1 = g_h[base + t + 256] + bo[t + 256] + x[base + t + 256];
    float s = h0 + h1;
    float q = h0*h0 + h1*h1;
#pragma unroll
    for (int m = 16; m >= 1; m >>= 1) {
        s += __shfl_xor_sync(0xffffffffu, s, m);
        q += __shfl_xor_sync(0xffffffffu, q, m);
    }
    __shared__ float ss[8], qq[8];
    int w = t >> 5;
    if ((t & 31) == 0) { ss[w] = s; qq[w] = q; }
    __syncthreads();
    float S2 = 0.f, Q2 = 0.f;
#pragma unroll
    for (int i = 0; i < 8; i++) { S2 += ss[i]; Q2 += qq[i]; }
    float mu  = S2 * (1.0f / 512.0f);
    float var = Q2 * (1.0f / 512.0f) - mu * mu;
    float inv = rsqrtf(var + 1e-12f);
    out[base + t]       = (h0 - mu) * inv * gamma[t]       + beta[t];
    out[base + t + 256] = (h1 - mu) * inv * gamma[t + 256] + beta[t + 256];
}

// ---------------------------------------------------------------------------
extern "C" void kernel_launch(void* const* d_in, const int* in_sizes, int n_in,
                              void* d_out, int out_size)
{
    const float* x     = (const float*)d_in[0];
    const float* mask  = (const float*)d_in[1];
    const int*   rb    = (const int*)  d_in[2];
    const float* Wq    = (const float*)d_in[3];
    const float* Wk    = (const float*)d_in[4];
    const float* Wv    = (const float*)d_in[5];
    const float* Wo    = (const float*)d_in[6];
    const float* bo    = (const float*)d_in[7];
    const float* gamma = (const float*)d_in[8];
    const float* beta  = (const float*)d_in[9];
    float* out = (float*)d_out;

    float* hp;
    __nv_bfloat16 *xb, *wtb;
    cudaGetSymbolAddress((void**)&hp, g_h);
    cudaGetSymbolAddress((void**)&xb, g_xb);
    cudaGetSymbolAddress((void**)&wtb, g_wtb);

    cudaFuncSetAttribute(gemm_wo,  cudaFuncAttributeMaxDynamicSharedMemorySize, GEMM_SMEM);
    cudaFuncSetAttribute(gemm_qkv, cudaFuncAttributeMaxDynamicSharedMemorySize, GEMM_SMEM);
    cudaFuncSetAttribute(attn_hmma, cudaFuncAttributeMaxDynamicSharedMemorySize, ATT_SMEM);

    prep_kernel<<<4096 + 1024, 256>>>(x, xb, Wq, Wk, Wv, Wo, wtb);

    dim3 gq(12, 64);                         // 1536/128 x 8192/128
    gemm_qkv<<<gq, 256, GEMM_SMEM>>>(xb, wtb);

    attn_hmma<<<16 * 92, 256, ATT_SMEM>>>(mask, rb);
    combine_kernel<<<64, 256>>>();

    dim3 go(4, 64);
    gemm_wo<<<go, 256, GEMM_SMEM>>>(xb, wtb + 3*262144, hp);

    ln_kernel<<<Bb * Ss, 256>>>(x, bo, gamma, beta, out);
}

// round 14
// speedup vs baseline: 1.0303x; 1.0128x over previous
#include <cuda_runtime.h>
#include <cuda_bf16.h>
#include <math.h>
#include <stdint.h>

#define Bb 2
#define Ss 4096
#define Dd 512
#define NROWS (Bb*Ss)      // 8192
#define NEGF -1000000000.0f

// ---------------- scratch (device globals: allocation-free) ----------------
__device__ float g_h[NROWS*Dd];
#define SLOT_F 4224
__device__ float g_part[512 * SLOT_F];
__device__ __align__(16) __nv_bfloat16 g_xb[NROWS*Dd];    // x bf16, later ctx bf16
__device__ __align__(16) __nv_bfloat16 g_wtb[4*Dd*Dd];    // W^T bf16 x4
__device__ __align__(16) __nv_bfloat16 g_qc[16ULL*4096*64];
__device__ __align__(16) __nv_bfloat16 g_kc[16ULL*4096*64];
__device__ __align__(16) __nv_bfloat16 g_vc[16ULL*4096*64];

// ---------------- PTX helpers ----------------
__device__ __forceinline__ uint32_t smem_u32(const void* p) {
    return (uint32_t)__cvta_generic_to_shared(p);
}
#define CPASYNC16(dst, src) \
    asm volatile("cp.async.cg.shared.global [%0], [%1], 16;" :: "r"(dst), "l"(src))
#define CPCOMMIT() asm volatile("cp.async.commit_group;" ::: "memory")
#define CPWAIT(n)  asm volatile("cp.async.wait_group %0;" :: "n"(n) : "memory")

#define LDSM_X4(r0, r1, r2, r3, a) \
    asm volatile("ldmatrix.sync.aligned.m8n8.x4.shared.b16 {%0,%1,%2,%3}, [%4];" \
                 : "=r"(r0), "=r"(r1), "=r"(r2), "=r"(r3) : "r"(a))
#define LDSM_X4T(r0, r1, r2, r3, a) \
    asm volatile("ldmatrix.sync.aligned.m8n8.x4.trans.shared.b16 {%0,%1,%2,%3}, [%4];" \
                 : "=r"(r0), "=r"(r1), "=r"(r2), "=r"(r3) : "r"(a))

#define MMA16816(D, A, B0, B1) \
    asm volatile("mma.sync.aligned.m16n8k16.row.col.f32.bf16.bf16.f32 " \
                 "{%0,%1,%2,%3},{%4,%5,%6,%7},{%8,%9},{%0,%1,%2,%3};" \
                 : "+f"((D)[0]), "+f"((D)[1]), "+f"((D)[2]), "+f"((D)[3]) \
                 : "r"((A)[0]), "r"((A)[1]), "r"((A)[2]), "r"((A)[3]), \
                   "r"(B0), "r"(B1))

__device__ __forceinline__ uint32_t pack_hi(float a, float b) {
    __nv_bfloat162 h = __floats2bfloat162_rn(a, b);
    return *(uint32_t*)&h;
}

// ---------------------------------------------------------------------------
// Fused prep: x -> bf16 (CTAs 0..4095) and 4x W -> W^T bf16 (CTAs 4096..5119)
// ---------------------------------------------------------------------------
__global__ __launch_bounds__(256) void prep_kernel(
    const float* __restrict__ X, __nv_bfloat16* __restrict__ Xb,
    const float* __restrict__ W0, const float* __restrict__ W1,
    const float* __restrict__ W2, const float* __restrict__ W3,
    __nv_bfloat16* __restrict__ Th)
{
    int cb = blockIdx.x;
    int t = threadIdx.x;
    if (cb < 4096) {
        size_t i0 = (size_t)cb * 1024 + t * 2;
        float2 v0 = *(const float2*)&X[i0];
        float2 v1 = *(const float2*)&X[i0 + 512];
        *(uint32_t*)&Xb[i0]       = pack_hi(v0.x, v0.y);
        *(uint32_t*)&Xb[i0 + 512] = pack_hi(v1.x, v1.y);
        return;
    }
    __shared__ float tile[32][33];
    int idx = cb - 4096;
    int z = idx >> 8;
    int rest = idx & 255;
    const float* W = (z == 0) ? W0 : (z == 1) ? W1 : (z == 2) ? W2 : W3;
    __nv_bfloat16* th = Th + (size_t)z * 262144;
    int n0 = (rest & 15) * 32, k0 = (rest >> 4) * 32;
    int tx = t & 31, ty = t >> 5;
#pragma unroll
    for (int j = 0; j < 32; j += 8)
        tile[ty + j][tx] = W[(size_t)(k0 + ty + j) * 512 + n0 + tx];
    __syncthreads();
#pragma unroll
    for (int j = 0; j < 32; j += 8) {
        int row = ty + j;
        th[(size_t)(n0 + row) * 512 + k0 + tx] = __float2bfloat16(tile[tx][row]);
    }
}

// ---------------------------------------------------------------------------
// Single-term GEMM mainloop (CTA 128x128, BK=64, K=512 -> 8 chunks, dbl buf)
// ---------------------------------------------------------------------------
#define GEMM_SMEM 65536

__device__ __forceinline__ void gemm_ld_chunk(const __nv_bfloat16* __restrict__ A,
                                              const __nv_bfloat16* __restrict__ Bt,
                                              int rowBase, int colBase, int k0,
                                              uint32_t Ab, uint32_t Bbuf, int t)
{
#pragma unroll
    for (int it = 0; it < 4; it++) {
        int idx = it * 256 + t;
        int r = idx >> 3, c = idx & 7;
        uint32_t d = Ab + r * 128 + ((c ^ (r & 7)) << 4);
        CPASYNC16(d, &A[(size_t)(rowBase + r) * 512 + k0 + c * 8]);
    }
#pragma unroll
    for (int it = 0; it < 4; it++) {
        int idx = it * 256 + t;
        int r = idx >> 3, c = idx & 7;
        uint32_t d = Bbuf + r * 128 + ((c ^ (r & 7)) << 4);
        CPASYNC16(d, &Bt[(size_t)(colBase + r) * 512 + k0 + c * 8]);
    }
    CPCOMMIT();
}

__device__ __forceinline__ void gemm1_mainloop(const __nv_bfloat16* A, const __nv_bfloat16* Bt,
                                               int rowBase, int colBase, uint32_t sbase, int t,
                                               float acc[2][8][4])
{
    int w = t >> 5, lane = t & 31;
    int wm = (w & 3) * 32, wn = (w >> 2) * 64;
    int laneA_row = (((lane >> 3) & 1) << 3) + (lane & 7);
    int laneA_ch  = (lane >> 4);
    int laneB_row = ((lane >> 4) << 3) + (lane & 7);
    int laneB_ch  = ((lane >> 3) & 1);

    gemm_ld_chunk(A, Bt, rowBase, colBase, 0, sbase, sbase + 16384u, t);

    for (int i = 0; i < 8; i++) {
        int buf = i & 1;
        if (i < 7) {
            uint32_t Ab = sbase + (buf ? 0u : 32768u);
            gemm_ld_chunk(A, Bt, rowBase, colBase, (i + 1) * 64, Ab, Ab + 16384u, t);
            CPWAIT(1);
        } else {
            CPWAIT(0);
        }
        __syncthreads();

        uint32_t Ab = sbase + (buf ? 32768u : 0u);
        uint32_t Bbuf = Ab + 16384u;
#pragma unroll
        for (int ks = 0; ks < 4; ks++) {
            uint32_t afr[2][4];
#pragma unroll
            for (int mt = 0; mt < 2; mt++) {
                int row = wm + mt * 16 + laneA_row;
                int ch  = ks * 2 + laneA_ch;
                uint32_t a = Ab + row * 128 + ((ch ^ (row & 7)) << 4);
                LDSM_X4(afr[mt][0], afr[mt][1], afr[mt][2], afr[mt][3], a);
            }
#pragma unroll
            for (int p = 0; p < 4; p++) {
                int row = wn + p * 16 + laneB_row;
                int ch  = ks * 2 + laneB_ch;
                uint32_t a = Bbuf + row * 128 + ((ch ^ (row & 7)) << 4);
                uint32_t b0, b1, b2, b3;
                LDSM_X4(b0, b1, b2, b3, a);
#pragma unroll
                for (int mt = 0; mt < 2; mt++) {
                    MMA16816(acc[mt][p*2],   afr[mt], b0, b1);
                    MMA16816(acc[mt][p*2+1], afr[mt], b2, b3);
                }
            }
        }
        __syncthreads();
    }
}

// Wo GEMM
__global__ __launch_bounds__(256, 2)
void gemm_wo(const __nv_bfloat16* __restrict__ A,
             const __nv_bfloat16* __restrict__ Bt,
             float* __restrict__ Y)
{
    extern __shared__ __align__(128) char sm[];
    uint32_t sbase = smem_u32(sm);
    int t = threadIdx.x, w = t >> 5, lane = t & 31;
    int rowBase = blockIdx.y * 128, colBase = blockIdx.x * 128;
    int wm = (w & 3) * 32, wn = (w >> 2) * 64;

    float acc[2][8][4];
#pragma unroll
    for (int mt = 0; mt < 2; mt++)
#pragma unroll
        for (int nt = 0; nt < 8; nt++)
#pragma unroll
            for (int e = 0; e < 4; e++) acc[mt][nt][e] = 0.f;

    gemm1_mainloop(A, Bt, rowBase, colBase, sbase, t, acc);

#pragma unroll
    for (int mt = 0; mt < 2; mt++)
#pragma unroll
        for (int nt = 0; nt < 8; nt++) {
            float* a4 = acc[mt][nt];
            int r0 = rowBase + wm + mt * 16 + (lane >> 2);
            int c0 = colBase + wn + nt * 8 + (lane & 3) * 2;
            *(float2*)&Y[(size_t)r0 * 512 + c0] = make_float2(a4[0], a4[1]);
            *(float2*)&Y[(size_t)(r0+8) * 512 + c0] = make_float2(a4[2], a4[3]);
        }
}

// QKV GEMM -> per-head bf16 [bh][s][64]
__global__ __launch_bounds__(256, 2)
void gemm_qkv(const __nv_bfloat16* __restrict__ A,
              const __nv_bfloat16* __restrict__ Bt)
{
    extern __shared__ __align__(128) char sm[];
    uint32_t sbase = smem_u32(sm);
    int t = threadIdx.x, w = t >> 5, lane = t & 31;
    int rowBase = blockIdx.y * 128, colBase = blockIdx.x * 128;
    int wm = (w & 3) * 32, wn = (w >> 2) * 64;

    float acc[2][8][4];
#pragma unroll
    for (int mt = 0; mt < 2; mt++)
#pragma unroll
        for (int nt = 0; nt < 8; nt++)
#pragma unroll
            for (int e = 0; e < 4; e++) acc[mt][nt][e] = 0.f;

    gemm1_mainloop(A, Bt, rowBase, colBase, sbase, t, acc);

    int tensor = colBase >> 9;
    float alpha = (tensor == 0) ? 0.125f : 1.0f;
    __nv_bfloat16* dst = (tensor == 0) ? g_qc : (tensor == 1) ? g_kc : g_vc;

#pragma unroll
    for (int mt = 0; mt < 2; mt++)
#pragma unroll
        for (int nt = 0; nt < 8; nt++) {
            float* a4 = acc[mt][nt];
            int r0 = rowBase + wm + mt * 16 + (lane >> 2);
            int cc = (colBase & 511) + wn + nt * 8 + (lane & 3) * 2;
            int hh = cc >> 6, dd = cc & 63;
            int b = r0 >> 12, s = r0 & 4095;
            size_t off = ((size_t)((b << 3) + hh) * 4096 + s) * 64 + dd;
            *(uint32_t*)&dst[off] = pack_hi(a4[0]*alpha, a4[1]*alpha);
            *(uint32_t*)&dst[off + 8ULL*64] = pack_hi(a4[2]*alpha, a4[3]*alpha);
        }
}

// ---------------------------------------------------------------------------
// HMMA attention (best-known config): 2-stage ring, hoisted Q, (256,2).
// ---------------------------------------------------------------------------
#define OFF_KS 8192
#define OFF_VS 24576
#define OFF_EX 40960
#define EX_PITCH 66
#define OFF_KM 57856
#define OFF_RL 58368
#define ATT_SMEM 58880

__device__ __forceinline__ int kb_of(bool mid, int qb, int chunk, int itk,
                                     const int* __restrict__ rand_blocks)
{
    if (!mid) return chunk * 8 + itk;
    if (itk < 3) return qb - 1 + itk;
    if (itk == 3) return 0;
    if (itk == 4) return 63;
    return rand_blocks[(qb - 2) * 3 + (itk - 5)];
}

__device__ __forceinline__ void attn_prefetch_kv(int bh, int kb, uint32_t KSb,
                                                 uint32_t VSb, int t)
{
    size_t koff = ((size_t)bh * 4096 + kb * 64) * 64;
#pragma unroll
    for (int it = 0; it < 2; it++) {
        int idx = it * 256 + t;
        int r = idx >> 3, c = idx & 7;
        CPASYNC16(KSb + r * 128 + ((c ^ (r & 7)) << 4), &g_kc[koff + r * 64 + c * 8]);
    }
#pragma unroll
    for (int it = 0; it < 2; it++) {
        int idx = it * 256 + t;
        int r = idx >> 3, c = idx & 7;
        CPASYNC16(VSb + r * 128 + ((c ^ (r & 7)) << 4), &g_vc[koff + r * 64 + c * 8]);
    }
    CPCOMMIT();
}

__global__ __launch_bounds__(256, 2)
void attn_hmma(const float* __restrict__ mask, const int* __restrict__ rand_blocks)
{
    extern __shared__ __align__(128) char sm[];
    uint32_t sb = smem_u32(sm);
    const uint32_t QS = sb;
    float* km   = (float*)(sm + OFF_KM);    // [2][64]
    float* redL = (float*)(sm + OFF_RL);
    float* ex   = (float*)(sm + OFF_EX);    // [64][EX_PITCH]

    int t = threadIdx.x, w = t >> 5, lane = t & 31;
    int wm = (w & 3) * 16;
    int wni = w >> 2;
    int wn  = wni * 32;

    int u  = blockIdx.x % 92;
    int bh = blockIdx.x / 92;
    int b  = bh >> 3, h = bh & 7;

    bool mid = (u < 60);
    int qb, chunk = 0, di = 0;
    if (mid) { qb = u + 2; }
    else {
        int d = u - 60;
        di = d >> 3; chunk = d & 7;
        qb = (di < 2) ? di : (60 + di);
    }

    // ---- prologue: Q + K0/V0 via cp.async (one group), km[0] ----
    {
        size_t qoff = ((size_t)bh * 4096 + qb * 64) * 64;
#pragma unroll
        for (int it = 0; it < 2; it++) {
            int idx = it * 256 + t;
            int r = idx >> 3, c = idx & 7;
            CPASYNC16(QS + r * 128 + ((c ^ (r & 7)) << 4), &g_qc[qoff + r * 64 + c * 8]);
        }
        int kb0 = kb_of(mid, qb, chunk, 0, rand_blocks);
        attn_prefetch_kv(bh, kb0, sb + OFF_KS, sb + OFF_VS, t);
        if (t < 64) km[t] = mask[b * 4096 + kb0 * 64 + t];
    }

    int r1 = wm + (lane >> 2), r2 = r1 + 8;
    float mq1 = mask[b * 4096 + qb * 64 + r1];
    float mq2 = mask[b * 4096 + qb * 64 + r2];

    float acc[8][4];
#pragma unroll
    for (int nn = 0; nn < 8; nn++)
#pragma unroll
        for (int e = 0; e < 4; e++) acc[nn][e] = 0.f;
    float ls1 = 0.f, ls2 = 0.f;

    int laneA_row = (((lane >> 3) & 1) << 3) + (lane & 7);
    int laneA_ch  = lane >> 4;
    int laneB_row = ((lane >> 4) << 3) + (lane & 7);
    int laneB_ch  = (lane >> 3) & 1;
    int laneV_row = lane & 15;
    int laneV_g   = lane >> 4;

    uint32_t qh[4][4];

    for (int itk = 0; itk < 8; itk++) {
        int buf = itk & 1;
        bool band = mid && (itk < 3);

        __syncthreads();
        if (itk < 7) {
            int kbn = kb_of(mid, qb, chunk, itk + 1, rand_blocks);
            attn_prefetch_kv(bh, kbn, sb + OFF_KS + (buf ^ 1) * 8192,
                             sb + OFF_VS + (buf ^ 1) * 8192, t);
            if (t < 64) km[(buf ^ 1) * 64 + t] = mask[b * 4096 + kbn * 64 + t];
            CPWAIT(1);
        } else {
            CPWAIT(0);
        }
        __syncthreads();

        if (itk == 0) {
            int row = wm + laneA_row;
#pragma unroll
            for (int ks = 0; ks < 4; ks++) {
                int ch = ks * 2 + laneA_ch;
                LDSM_X4(qh[ks][0], qh[ks][1], qh[ks][2], qh[ks][3],
                        QS + row * 128 + ((ch ^ (row & 7)) << 4));
            }
        }

        uint32_t KSb = sb + OFF_KS + buf * 8192;
        uint32_t VSb = sb + OFF_VS + buf * 8192;
        const float* kmask_s = km + buf * 64;

        // ---- QK ----
        float sc[4][4];
#pragma unroll
        for (int nt = 0; nt < 4; nt++)
#pragma unroll
            for (int e = 0; e < 4; e++) sc[nt][e] = 0.f;

#pragma unroll
        for (int ks = 0; ks < 4; ks++) {
            int kc2 = ks * 2;
#pragma unroll
            for (int g = 0; g < 2; g++) {
                uint32_t kh[4];
                int row = wn + g * 16 + laneB_row;
                int ch = kc2 + laneB_ch;
                LDSM_X4(kh[0], kh[1], kh[2], kh[3],
                        KSb + row * 128 + ((ch ^ (row & 7)) << 4));
                MMA16816(sc[g*2],   qh[ks], kh[0], kh[1]);
                MMA16816(sc[g*2+1], qh[ks], kh[2], kh[3]);
            }
        }

        // ---- mask ----
#pragma unroll
        for (int nt = 0; nt < 4; nt++) {
            int col = wn + nt * 8 + (lane & 3) * 2;
            float mk0 = kmask_s[col], mk1 = kmask_s[col + 1];
            float m00 = band ? mk0 * mq1 : mk0;
            float m01 = band ? mk1 * mq1 : mk1;
            float m10 = band ? mk0 * mq2 : mk0;
            float m11 = band ? mk1 * mq2 : mk1;
            sc[nt][0] += (1.0f - m00) * NEGF;
            sc[nt][1] += (1.0f - m01) * NEGF;
            sc[nt][2] += (1.0f - m10) * NEGF;
            sc[nt][3] += (1.0f - m11) * NEGF;
        }

        // ---- exp + bf16 pack ----
        uint32_t aph[2][4];
#pragma unroll
        for (int nt = 0; nt < 4; nt++) {
            float p00 = __expf(sc[nt][0]), p01 = __expf(sc[nt][1]);
            float p10 = __expf(sc[nt][2]), p11 = __expf(sc[nt][3]);
            ls1 += p00 + p01; ls2 += p10 + p11;
            int j = nt >> 1, hf = (nt & 1) * 2;
            aph[j][hf]     = pack_hi(p00, p01);
            aph[j][hf + 1] = pack_hi(p10, p11);
        }

        // ---- PV ----
#pragma unroll
        for (int j = 0; j < 2; j++) {
            int vrow = wn + j * 16 + laneV_row;
            uint32_t vbase = VSb + vrow * 128;
            int sw = (vrow & 7) << 4;
#pragma unroll
            for (int np = 0; np < 4; np++) {
                uint32_t vh4[4];
                int ch = np * 2 + laneV_g;
                LDSM_X4T(vh4[0], vh4[1], vh4[2], vh4[3], vbase + ((ch << 4) ^ sw));
                MMA16816(acc[np*2],   aph[j], vh4[0], vh4[1]);
                MMA16816(acc[np*2+1], aph[j], vh4[2], vh4[3]);
            }
        }
    }

    // ---- final ls combine ----
    ls1 += __shfl_xor_sync(0xffffffffu, ls1, 1);
    ls1 += __shfl_xor_sync(0xffffffffu, ls1, 2);
    ls2 += __shfl_xor_sync(0xffffffffu, ls2, 1);
    ls2 += __shfl_xor_sync(0xffffffffu, ls2, 2);
    if ((lane & 3) == 0) {
        redL[wni * 64 + r1] = ls1;
        redL[wni * 64 + r2] = ls2;
    }
    __syncthreads();
    ls1 = redL[r1] + redL[64 + r1];
    ls2 = redL[r2] + redL[64 + r2];

    // ---- cross-half acc reduction ----
    if (wni == 1) {
#pragma unroll
        for (int nn = 0; nn < 8; nn++) {
            int col = nn * 8 + (lane & 3) * 2;
            *(float2*)&ex[r1 * EX_PITCH + col] = make_float2(acc[nn][0], acc[nn][1]);
            *(float2*)&ex[r2 * EX_PITCH + col] = make_float2(acc[nn][2], acc[nn][3]);
        }
    }
    __syncthreads();
    if (wni == 0) {
#pragma unroll
        for (int nn = 0; nn < 8; nn++) {
            int col = nn * 8 + (lane & 3) * 2;
            float2 v1 = *(float2*)&ex[r1 * EX_PITCH + col];
            float2 v2 = *(float2*)&ex[r2 * EX_PITCH + col];
            acc[nn][0] += v1.x; acc[nn][1] += v1.y;
            acc[nn][2] += v2.x; acc[nn][3] += v2.y;
        }

        if (mid) {
            float inv1 = 1.0f / ls1, inv2 = 1.0f / ls2;
#pragma unroll
            for (int nn = 0; nn < 8; nn++) {
                int col = nn * 8 + (lane & 3) * 2;
                size_t o1 = ((size_t)(b * 4096 + qb * 64 + r1)) * 512 + h * 64 + col;
                size_t o2 = ((size_t)(b * 4096 + qb * 64 + r2)) * 512 + h * 64 + col;
                *(uint32_t*)&g_xb[o1] = pack_hi(acc[nn][0] * inv1, acc[nn][1] * inv1);
                *(uint32_t*)&g_xb[o2] = pack_hi(acc[nn][2] * inv2, acc[nn][3] * inv2);
            }
        } else {
            int slot = (bh * 4 + di) * 8 + chunk;
            float* p = g_part + (size_t)slot * SLOT_F;
#pragma unroll
            for (int nn = 0; nn < 8; nn++) {
                int col = nn * 8 + (lane & 3) * 2;
                *(float2*)&p[r1 * 64 + col] = make_float2(acc[nn][0], acc[nn][1]);
                *(float2*)&p[r2 * 64 + col] = make_float2(acc[nn][2], acc[nn][3]);
            }
            if ((lane & 3) == 0) {
                p[4096 + r1] = ls1;
                p[4096 + r2] = ls2;
            }
        }
    }
}

// ---------------------------------------------------------------------------
// Combine: 256 CTAs (64 groups x 4 slices of 16 rows); coalesced float4 sweep.
// ---------------------------------------------------------------------------
__global__ __launch_bounds__(256) void combine_kernel()
{
    __shared__ float sinv[16];
    int blk = blockIdx.x;
    int g  = blk >> 2;          // dense group
    int sl = blk & 3;           // 16-row slice
    int bh = g >> 2, di = g & 3;
    int qb = (di < 2) ? di : (60 + di);
    int b  = bh >> 3, h = bh & 7;
    int t  = threadIdx.x;

    const float* base = g_part + (size_t)(g * 8) * SLOT_F;
    if (t < 16) {
        int row = sl * 16 + t;
        float L = 0.f;
#pragma unroll
        for (int s = 0; s < 8; s++) L += base[s*SLOT_F + 4096 + row];
        sinv[t] = 1.0f / L;
    }
    __syncthreads();

    int idx4 = sl * 256 + t;                 // float4 index within 64x64 tile
    float4 o = make_float4(0.f, 0.f, 0.f, 0.f);
#pragma unroll
    for (int s = 0; s < 8; s++) {
        float4 v = *(const float4*)&base[s*SLOT_F + idx4 * 4];
        o.x += v.x; o.y += v.y; o.z += v.z; o.w += v.w;
    }
    int row = idx4 >> 4;
    int col = (idx4 & 15) * 4;
    float inv = sinv[row - sl * 16];
    uint2 pk = make_uint2(pack_hi(o.x * inv, o.y * inv),
                          pack_hi(o.z * inv, o.w * inv));
    size_t rowBase = ((size_t)(b * 4096 + qb * 64)) * 512 + h * 64;
    *(uint2*)&g_xb[rowBase + (size_t)row * 512 + col] = pk;
}

// ---------------------------------------------------------------------------
__global__ __launch_bounds__(256) void ln_kernel(const float* __restrict__ x,
                                                 const float* __restrict__ bo,
                                                 const float* __restrict__ gamma,
                                                 const float* __restrict__ beta,
                                                 float* __restrict__ out)
{
    int row = blockIdx.x;
    int t = threadIdx.x;
    size_t base = (size_t)row * 512;
    float h0 = g_h[base + t]       + bo[t]       + x[base + t];
    float h1 = g_h[base + t + 256] + bo[t + 256] + x[base + t + 256];
    float s = h0 + h1;
    float q = h0*h0 + h1*h1;
#pragma unroll
    for (int m = 16; m >= 1; m >>= 1) {
        s += __shfl_xor_sync(0xffffffffu, s, m);
        q += __shfl_xor_sync(0xffffffffu, q, m);
    }
    __shared__ float ss[8], qq[8];
    int w = t >> 5;
    if ((t & 31) == 0) { ss[w] = s; qq[w] = q; }
    __syncthreads();
    float S2 = 0.f, Q2 = 0.f;
#pragma unroll
    for (int i = 0; i < 8; i++) { S2 += ss[i]; Q2 += qq[i]; }
    float mu  = S2 * (1.0f / 512.0f);
    float var = Q2 * (1.0f / 512.0f) - mu * mu;
    float inv = rsqrtf(var + 1e-12f);
    out[base + t]       = (h0 - mu) * inv * gamma[t]       + beta[t];
    out[base + t + 256] = (h1 - mu) * inv * gamma[t + 256] + beta[t + 256];
}

// ---------------------------------------------------------------------------
extern "C" void kernel_launch(void* const* d_in, const int* in_sizes, int n_in,
                              void* d_out, int out_size)
{
    const float* x     = (const float*)d_in[0];
    const float* mask  = (const float*)d_in[1];
    const int*   rb    = (const int*)  d_in[2];
    const float* Wq    = (const float*)d_in[3];
    const float* Wk    = (const float*)d_in[4];
    const float* Wv    = (const float*)d_in[5];
    const float* Wo    = (const float*)d_in[6];
    const float* bo    = (const float*)d_in[7];
    const float* gamma = (const float*)d_in[8];
    const float* beta  = (const float*)d_in[9];
    float* out = (float*)d_out;

    float* hp;
    __nv_bfloat16 *xb, *wtb;
    cudaGetSymbolAddress((void**)&hp, g_h);
    cudaGetSymbolAddress((void**)&xb, g_xb);
    cudaGetSymbolAddress((void**)&wtb, g_wtb);

    cudaFuncSetAttribute(gemm_wo,  cudaFuncAttributeMaxDynamicSharedMemorySize, GEMM_SMEM);
    cudaFuncSetAttribute(gemm_qkv, cudaFuncAttributeMaxDynamicSharedMemorySize, GEMM_SMEM);
    cudaFuncSetAttribute(attn_hmma, cudaFuncAttributeMaxDynamicSharedMemorySize, ATT_SMEM);

    prep_kernel<<<4096 + 1024, 256>>>(x, xb, Wq, Wk, Wv, Wo, wtb);

    dim3 gq(12, 64);                         // 1536/128 x 8192/128
    gemm_qkv<<<gq, 256, GEMM_SMEM>>>(xb, wtb);

    attn_hmma<<<16 * 92, 256, ATT_SMEM>>>(mask, rb);
    combine_kernel<<<256, 256>>>();

    dim3 go(4, 64);
    gemm_wo<<<go, 256, GEMM_SMEM>>>(xb, wtb + 3*262144, hp);

    ln_kernel<<<Bb * Ss, 256>>>(x, bo, gamma, beta, out);
}

// round 15
// speedup vs baseline: 1.0321x; 1.0018x over previous
#include <cuda_runtime.h>
#include <cuda_bf16.h>
#include <math.h>
#include <stdint.h>

#define Bb 2
#define Ss 4096
#define Dd 512
#define NROWS (Bb*Ss)      // 8192
#define NEGF -1000000000.0f

// ---------------- scratch (device globals: allocation-free) ----------------
__device__ float g_h[NROWS*Dd];
__device__ __align__(16) __nv_bfloat16 g_partb[512ULL*4096];  // dense partials bf16
__device__ float g_partl[512*64];                             // dense partial ls
__device__ __align__(16) __nv_bfloat16 g_xb[NROWS*Dd];    // x bf16, later ctx bf16
__device__ __align__(16) __nv_bfloat16 g_wtb[4*Dd*Dd];    // W^T bf16 x4
__device__ __align__(16) __nv_bfloat16 g_qc[16ULL*4096*64];
__device__ __align__(16) __nv_bfloat16 g_kc[16ULL*4096*64];
__device__ __align__(16) __nv_bfloat16 g_vc[16ULL*4096*64];

// ---------------- PTX helpers ----------------
__device__ __forceinline__ uint32_t smem_u32(const void* p) {
    return (uint32_t)__cvta_generic_to_shared(p);
}
#define CPASYNC16(dst, src) \
    asm volatile("cp.async.cg.shared.global [%0], [%1], 16;" :: "r"(dst), "l"(src))
#define CPCOMMIT() asm volatile("cp.async.commit_group;" ::: "memory")
#define CPWAIT(n)  asm volatile("cp.async.wait_group %0;" :: "n"(n) : "memory")

#define LDSM_X4(r0, r1, r2, r3, a) \
    asm volatile("ldmatrix.sync.aligned.m8n8.x4.shared.b16 {%0,%1,%2,%3}, [%4];" \
                 : "=r"(r0), "=r"(r1), "=r"(r2), "=r"(r3) : "r"(a))
#define LDSM_X4T(r0, r1, r2, r3, a) \
    asm volatile("ldmatrix.sync.aligned.m8n8.x4.trans.shared.b16 {%0,%1,%2,%3}, [%4];" \
                 : "=r"(r0), "=r"(r1), "=r"(r2), "=r"(r3) : "r"(a))

#define MMA16816(D, A, B0, B1) \
    asm volatile("mma.sync.aligned.m16n8k16.row.col.f32.bf16.bf16.f32 " \
                 "{%0,%1,%2,%3},{%4,%5,%6,%7},{%8,%9},{%0,%1,%2,%3};" \
                 : "+f"((D)[0]), "+f"((D)[1]), "+f"((D)[2]), "+f"((D)[3]) \
                 : "r"((A)[0]), "r"((A)[1]), "r"((A)[2]), "r"((A)[3]), \
                   "r"(B0), "r"(B1))

__device__ __forceinline__ uint32_t pack_hi(float a, float b) {
    __nv_bfloat162 h = __floats2bfloat162_rn(a, b);
    return *(uint32_t*)&h;
}
__device__ __forceinline__ float2 unpk(uint32_t u) {
    __nv_bfloat162 h = *(__nv_bfloat162*)&u;
    return make_float2(__bfloat162float(h.x), __bfloat162float(h.y));
}

// ---------------------------------------------------------------------------
// Fused prep: x -> bf16 (CTAs 0..4095) and 4x W -> W^T bf16 (CTAs 4096..5119)
// ---------------------------------------------------------------------------
__global__ __launch_bounds__(256) void prep_kernel(
    const float* __restrict__ X, __nv_bfloat16* __restrict__ Xb,
    const float* __restrict__ W0, const float* __restrict__ W1,
    const float* __restrict__ W2, const float* __restrict__ W3,
    __nv_bfloat16* __restrict__ Th)
{
    int cb = blockIdx.x;
    int t = threadIdx.x;
    if (cb < 4096) {
        size_t i0 = (size_t)cb * 1024 + t * 2;
        float2 v0 = *(const float2*)&X[i0];
        float2 v1 = *(const float2*)&X[i0 + 512];
        *(uint32_t*)&Xb[i0]       = pack_hi(v0.x, v0.y);
        *(uint32_t*)&Xb[i0 + 512] = pack_hi(v1.x, v1.y);
        return;
    }
    __shared__ float tile[32][33];
    int idx = cb - 4096;
    int z = idx >> 8;
    int rest = idx & 255;
    const float* W = (z == 0) ? W0 : (z == 1) ? W1 : (z == 2) ? W2 : W3;
    __nv_bfloat16* th = Th + (size_t)z * 262144;
    int n0 = (rest & 15) * 32, k0 = (rest >> 4) * 32;
    int tx = t & 31, ty = t >> 5;
#pragma unroll
    for (int j = 0; j < 32; j += 8)
        tile[ty + j][tx] = W[(size_t)(k0 + ty + j) * 512 + n0 + tx];
    __syncthreads();
#pragma unroll
    for (int j = 0; j < 32; j += 8) {
        int row = ty + j;
        th[(size_t)(n0 + row) * 512 + k0 + tx] = __float2bfloat16(tile[tx][row]);
    }
}

// ---------------------------------------------------------------------------
// Single-term GEMM mainloop (CTA 128x128, BK=64, K=512 -> 8 chunks, dbl buf)
// ---------------------------------------------------------------------------
#define GEMM_SMEM 65536

__device__ __forceinline__ void gemm_ld_chunk(const __nv_bfloat16* __restrict__ A,
                                              const __nv_bfloat16* __restrict__ Bt,
                                              int rowBase, int colBase, int k0,
                                              uint32_t Ab, uint32_t Bbuf, int t)
{
#pragma unroll
    for (int it = 0; it < 4; it++) {
        int idx = it * 256 + t;
        int r = idx >> 3, c = idx & 7;
        uint32_t d = Ab + r * 128 + ((c ^ (r & 7)) << 4);
        CPASYNC16(d, &A[(size_t)(rowBase + r) * 512 + k0 + c * 8]);
    }
#pragma unroll
    for (int it = 0; it < 4; it++) {
        int idx = it * 256 + t;
        int r = idx >> 3, c = idx & 7;
        uint32_t d = Bbuf + r * 128 + ((c ^ (r & 7)) << 4);
        CPASYNC16(d, &Bt[(size_t)(colBase + r) * 512 + k0 + c * 8]);
    }
    CPCOMMIT();
}

__device__ __forceinline__ void gemm1_mainloop(const __nv_bfloat16* A, const __nv_bfloat16* Bt,
                                               int rowBase, int colBase, uint32_t sbase, int t,
                                               float acc[2][8][4])
{
    int w = t >> 5, lane = t & 31;
    int wm = (w & 3) * 32, wn = (w >> 2) * 64;
    int laneA_row = (((lane >> 3) & 1) << 3) + (lane & 7);
    int laneA_ch  = (lane >> 4);
    int laneB_row = ((lane >> 4) << 3) + (lane & 7);
    int laneB_ch  = ((lane >> 3) & 1);

    gemm_ld_chunk(A, Bt, rowBase, colBase, 0, sbase, sbase + 16384u, t);

    for (int i = 0; i < 8; i++) {
        int buf = i & 1;
        if (i < 7) {
            uint32_t Ab = sbase + (buf ? 0u : 32768u);
            gemm_ld_chunk(A, Bt, rowBase, colBase, (i + 1) * 64, Ab, Ab + 16384u, t);
            CPWAIT(1);
        } else {
            CPWAIT(0);
        }
        __syncthreads();

        uint32_t Ab = sbase + (buf ? 32768u : 0u);
        uint32_t Bbuf = Ab + 16384u;
#pragma unroll
        for (int ks = 0; ks < 4; ks++) {
            uint32_t afr[2][4];
#pragma unroll
            for (int mt = 0; mt < 2; mt++) {
                int row = wm + mt * 16 + laneA_row;
                int ch  = ks * 2 + laneA_ch;
                uint32_t a = Ab + row * 128 + ((ch ^ (row & 7)) << 4);
                LDSM_X4(afr[mt][0], afr[mt][1], afr[mt][2], afr[mt][3], a);
            }
#pragma unroll
            for (int p = 0; p < 4; p++) {
                int row = wn + p * 16 + laneB_row;
                int ch  = ks * 2 + laneB_ch;
                uint32_t a = Bbuf + row * 128 + ((ch ^ (row & 7)) << 4);
                uint32_t b0, b1, b2, b3;
                LDSM_X4(b0, b1, b2, b3, a);
#pragma unroll
                for (int mt = 0; mt < 2; mt++) {
                    MMA16816(acc[mt][p*2],   afr[mt], b0, b1);
                    MMA16816(acc[mt][p*2+1], afr[mt], b2, b3);
                }
            }
        }
        __syncthreads();
    }
}

// Wo GEMM: Y = ctx@Wo^T + bo + x (residual+bias fused into epilogue)
__global__ __launch_bounds__(256, 2)
void gemm_wo(const __nv_bfloat16* __restrict__ A,
             const __nv_bfloat16* __restrict__ Bt,
             const float* __restrict__ X,
             const float* __restrict__ bo2,
             float* __restrict__ Y)
{
    extern __shared__ __align__(128) char sm[];
    uint32_t sbase = smem_u32(sm);
    int t = threadIdx.x, w = t >> 5, lane = t & 31;
    int rowBase = blockIdx.y * 128, colBase = blockIdx.x * 128;
    int wm = (w & 3) * 32, wn = (w >> 2) * 64;

    float acc[2][8][4];
#pragma unroll
    for (int mt = 0; mt < 2; mt++)
#pragma unroll
        for (int nt = 0; nt < 8; nt++)
#pragma unroll
            for (int e = 0; e < 4; e++) acc[mt][nt][e] = 0.f;

    gemm1_mainloop(A, Bt, rowBase, colBase, sbase, t, acc);

#pragma unroll
    for (int mt = 0; mt < 2; mt++)
#pragma unroll
        for (int nt = 0; nt < 8; nt++) {
            float* a4 = acc[mt][nt];
            int r0 = rowBase + wm + mt * 16 + (lane >> 2);
            int c0 = colBase + wn + nt * 8 + (lane & 3) * 2;
            float2 bv = *(const float2*)&bo2[c0];
            float2 x0 = *(const float2*)&X[(size_t)r0 * 512 + c0];
            float2 x1 = *(const float2*)&X[(size_t)(r0 + 8) * 512 + c0];
            *(float2*)&Y[(size_t)r0 * 512 + c0] =
                make_float2(a4[0] + bv.x + x0.x, a4[1] + bv.y + x0.y);
            *(float2*)&Y[(size_t)(r0+8) * 512 + c0] =
                make_float2(a4[2] + bv.x + x1.x, a4[3] + bv.y + x1.y);
        }
}

// QKV GEMM -> per-head bf16 [bh][s][64]
__global__ __launch_bounds__(256, 2)
void gemm_qkv(const __nv_bfloat16* __restrict__ A,
              const __nv_bfloat16* __restrict__ Bt)
{
    extern __shared__ __align__(128) char sm[];
    uint32_t sbase = smem_u32(sm);
    int t = threadIdx.x, w = t >> 5, lane = t & 31;
    int rowBase = blockIdx.y * 128, colBase = blockIdx.x * 128;
    int wm = (w & 3) * 32, wn = (w >> 2) * 64;

    float acc[2][8][4];
#pragma unroll
    for (int mt = 0; mt < 2; mt++)
#pragma unroll
        for (int nt = 0; nt < 8; nt++)
#pragma unroll
            for (int e = 0; e < 4; e++) acc[mt][nt][e] = 0.f;

    gemm1_mainloop(A, Bt, rowBase, colBase, sbase, t, acc);

    int tensor = colBase >> 9;
    float alpha = (tensor == 0) ? 0.125f : 1.0f;
    __nv_bfloat16* dst = (tensor == 0) ? g_qc : (tensor == 1) ? g_kc : g_vc;

#pragma unroll
    for (int mt = 0; mt < 2; mt++)
#pragma unroll
        for (int nt = 0; nt < 8; nt++) {
            float* a4 = acc[mt][nt];
            int r0 = rowBase + wm + mt * 16 + (lane >> 2);
            int cc = (colBase & 511) + wn + nt * 8 + (lane & 3) * 2;
            int hh = cc >> 6, dd = cc & 63;
            int b = r0 >> 12, s = r0 & 4095;
            size_t off = ((size_t)((b << 3) + hh) * 4096 + s) * 64 + dd;
            *(uint32_t*)&dst[off] = pack_hi(a4[0]*alpha, a4[1]*alpha);
            *(uint32_t*)&dst[off + 8ULL*64] = pack_hi(a4[2]*alpha, a4[3]*alpha);
        }
}

// ---------------------------------------------------------------------------
// HMMA attention (best-known config): 2-stage ring, hoisted Q, (256,2).
// ---------------------------------------------------------------------------
#define OFF_KS 8192
#define OFF_VS 24576
#define OFF_EX 40960
#define EX_PITCH 66
#define OFF_KM 57856
#define OFF_RL 58368
#define ATT_SMEM 58880

__device__ __forceinline__ int kb_of(bool mid, int qb, int chunk, int itk,
                                     const int* __restrict__ rand_blocks)
{
    if (!mid) return chunk * 8 + itk;
    if (itk < 3) return qb - 1 + itk;
    if (itk == 3) return 0;
    if (itk == 4) return 63;
    return rand_blocks[(qb - 2) * 3 + (itk - 5)];
}

__device__ __forceinline__ void attn_prefetch_kv(int bh, int kb, uint32_t KSb,
                                                 uint32_t VSb, int t)
{
    size_t koff = ((size_t)bh * 4096 + kb * 64) * 64;
#pragma unroll
    for (int it = 0; it < 2; it++) {
        int idx = it * 256 + t;
        int r = idx >> 3, c = idx & 7;
        CPASYNC16(KSb + r * 128 + ((c ^ (r & 7)) << 4), &g_kc[koff + r * 64 + c * 8]);
    }
#pragma unroll
    for (int it = 0; it < 2; it++) {
        int idx = it * 256 + t;
        int r = idx >> 3, c = idx & 7;
        CPASYNC16(VSb + r * 128 + ((c ^ (r & 7)) << 4), &g_vc[koff + r * 64 + c * 8]);
    }
    CPCOMMIT();
}

__global__ __launch_bounds__(256, 2)
void attn_hmma(const float* __restrict__ mask, const int* __restrict__ rand_blocks)
{
    extern __shared__ __align__(128) char sm[];
    uint32_t sb = smem_u32(sm);
    const uint32_t QS = sb;
    float* km   = (float*)(sm + OFF_KM);    // [2][64]
    float* redL = (float*)(sm + OFF_RL);
    float* ex   = (float*)(sm + OFF_EX);    // [64][EX_PITCH]

    int t = threadIdx.x, w = t >> 5, lane = t & 31;
    int wm = (w & 3) * 16;
    int wni = w >> 2;
    int wn  = wni * 32;

    int u  = blockIdx.x % 92;
    int bh = blockIdx.x / 92;
    int b  = bh >> 3, h = bh & 7;

    bool mid = (u < 60);
    int qb, chunk = 0, di = 0;
    if (mid) { qb = u + 2; }
    else {
        int d = u - 60;
        di = d >> 3; chunk = d & 7;
        qb = (di < 2) ? di : (60 + di);
    }

    // ---- prologue: Q + K0/V0 via cp.async (one group), km[0] ----
    {
        size_t qoff = ((size_t)bh * 4096 + qb * 64) * 64;
#pragma unroll
        for (int it = 0; it < 2; it++) {
            int idx = it * 256 + t;
            int r = idx >> 3, c = idx & 7;
            CPASYNC16(QS + r * 128 + ((c ^ (r & 7)) << 4), &g_qc[qoff + r * 64 + c * 8]);
        }
        int kb0 = kb_of(mid, qb, chunk, 0, rand_blocks);
        attn_prefetch_kv(bh, kb0, sb + OFF_KS, sb + OFF_VS, t);
        if (t < 64) km[t] = mask[b * 4096 + kb0 * 64 + t];
    }

    int r1 = wm + (lane >> 2), r2 = r1 + 8;
    float mq1 = mask[b * 4096 + qb * 64 + r1];
    float mq2 = mask[b * 4096 + qb * 64 + r2];

    float acc[8][4];
#pragma unroll
    for (int nn = 0; nn < 8; nn++)
#pragma unroll
        for (int e = 0; e < 4; e++) acc[nn][e] = 0.f;
    float ls1 = 0.f, ls2 = 0.f;

    int laneA_row = (((lane >> 3) & 1) << 3) + (lane & 7);
    int laneA_ch  = lane >> 4;
    int laneB_row = ((lane >> 4) << 3) + (lane & 7);
    int laneB_ch  = (lane >> 3) & 1;
    int laneV_row = lane & 15;
    int laneV_g   = lane >> 4;

    uint32_t qh[4][4];

    for (int itk = 0; itk < 8; itk++) {
        int buf = itk & 1;
        bool band = mid && (itk < 3);

        __syncthreads();
        if (itk < 7) {
            int kbn = kb_of(mid, qb, chunk, itk + 1, rand_blocks);
            attn_prefetch_kv(bh, kbn, sb + OFF_KS + (buf ^ 1) * 8192,
                             sb + OFF_VS + (buf ^ 1) * 8192, t);
            if (t < 64) km[(buf ^ 1) * 64 + t] = mask[b * 4096 + kbn * 64 + t];
            CPWAIT(1);
        } else {
            CPWAIT(0);
        }
        __syncthreads();

        if (itk == 0) {
            int row = wm + laneA_row;
#pragma unroll
            for (int ks = 0; ks < 4; ks++) {
                int ch = ks * 2 + laneA_ch;
                LDSM_X4(qh[ks][0], qh[ks][1], qh[ks][2], qh[ks][3],
                        QS + row * 128 + ((ch ^ (row & 7)) << 4));
            }
        }

        uint32_t KSb = sb + OFF_KS + buf * 8192;
        uint32_t VSb = sb + OFF_VS + buf * 8192;
        const float* kmask_s = km + buf * 64;

        // ---- QK ----
        float sc[4][4];
#pragma unroll
        for (int nt = 0; nt < 4; nt++)
#pragma unroll
            for (int e = 0; e < 4; e++) sc[nt][e] = 0.f;

#pragma unroll
        for (int ks = 0; ks < 4; ks++) {
            int kc2 = ks * 2;
#pragma unroll
            for (int g = 0; g < 2; g++) {
                uint32_t kh[4];
                int row = wn + g * 16 + laneB_row;
                int ch = kc2 + laneB_ch;
                LDSM_X4(kh[0], kh[1], kh[2], kh[3],
                        KSb + row * 128 + ((ch ^ (row & 7)) << 4));
                MMA16816(sc[g*2],   qh[ks], kh[0], kh[1]);
                MMA16816(sc[g*2+1], qh[ks], kh[2], kh[3]);
            }
        }

        // ---- mask ----
#pragma unroll
        for (int nt = 0; nt < 4; nt++) {
            int col = wn + nt * 8 + (lane & 3) * 2;
            float mk0 = kmask_s[col], mk1 = kmask_s[col + 1];
            float m00 = band ? mk0 * mq1 : mk0;
            float m01 = band ? mk1 * mq1 : mk1;
            float m10 = band ? mk0 * mq2 : mk0;
            float m11 = band ? mk1 * mq2 : mk1;
            sc[nt][0] += (1.0f - m00) * NEGF;
            sc[nt][1] += (1.0f - m01) * NEGF;
            sc[nt][2] += (1.0f - m10) * NEGF;
            sc[nt][3] += (1.0f - m11) * NEGF;
        }

        // ---- exp + bf16 pack ----
        uint32_t aph[2][4];
#pragma unroll
        for (int nt = 0; nt < 4; nt++) {
            float p00 = __expf(sc[nt][0]), p01 = __expf(sc[nt][1]);
            float p10 = __expf(sc[nt][2]), p11 = __expf(sc[nt][3]);
            ls1 += p00 + p01; ls2 += p10 + p11;
            int j = nt >> 1, hf = (nt & 1) * 2;
            aph[j][hf]     = pack_hi(p00, p01);
            aph[j][hf + 1] = pack_hi(p10, p11);
        }

        // ---- PV ----
#pragma unroll
        for (int j = 0; j < 2; j++) {
            int vrow = wn + j * 16 + laneV_row;
            uint32_t vbase = VSb + vrow * 128;
            int sw = (vrow & 7) << 4;
#pragma unroll
            for (int np = 0; np < 4; np++) {
                uint32_t vh4[4];
                int ch = np * 2 + laneV_g;
                LDSM_X4T(vh4[0], vh4[1], vh4[2], vh4[3], vbase + ((ch << 4) ^ sw));
                MMA16816(acc[np*2],   aph[j], vh4[0], vh4[1]);
                MMA16816(acc[np*2+1], aph[j], vh4[2], vh4[3]);
            }
        }
    }

    // ---- final ls combine ----
    ls1 += __shfl_xor_sync(0xffffffffu, ls1, 1);
    ls1 += __shfl_xor_sync(0xffffffffu, ls1, 2);
    ls2 += __shfl_xor_sync(0xffffffffu, ls2, 1);
    ls2 += __shfl_xor_sync(0xffffffffu, ls2, 2);
    if ((lane & 3) == 0) {
        redL[wni * 64 + r1] = ls1;
        redL[wni * 64 + r2] = ls2;
    }
    __syncthreads();
    ls1 = redL[r1] + redL[64 + r1];
    ls2 = redL[r2] + redL[64 + r2];

    // ---- cross-half acc reduction ----
    if (wni == 1) {
#pragma unroll
        for (int nn = 0; nn < 8; nn++) {
            int col = nn * 8 + (lane & 3) * 2;
            *(float2*)&ex[r1 * EX_PITCH + col] = make_float2(acc[nn][0], acc[nn][1]);
            *(float2*)&ex[r2 * EX_PITCH + col] = make_float2(acc[nn][2], acc[nn][3]);
        }
    }
    __syncthreads();
    if (wni == 0) {
#pragma unroll
        for (int nn = 0; nn < 8; nn++) {
            int col = nn * 8 + (lane & 3) * 2;
            float2 v1 = *(float2*)&ex[r1 * EX_PITCH + col];
            float2 v2 = *(float2*)&ex[r2 * EX_PITCH + col];
            acc[nn][0] += v1.x; acc[nn][1] += v1.y;
            acc[nn][2] += v2.x; acc[nn][3] += v2.y;
        }

        if (mid) {
            float inv1 = 1.0f / ls1, inv2 = 1.0f / ls2;
#pragma unroll
            for (int nn = 0; nn < 8; nn++) {
                int col = nn * 8 + (lane & 3) * 2;
                size_t o1 = ((size_t)(b * 4096 + qb * 64 + r1)) * 512 + h * 64 + col;
                size_t o2 = ((size_t)(b * 4096 + qb * 64 + r2)) * 512 + h * 64 + col;
                *(uint32_t*)&g_xb[o1] = pack_hi(acc[nn][0] * inv1, acc[nn][1] * inv1);
                *(uint32_t*)&g_xb[o2] = pack_hi(acc[nn][2] * inv2, acc[nn][3] * inv2);
            }
        } else {
            int slot = (bh * 4 + di) * 8 + chunk;
            __nv_bfloat16* pb = g_partb + (size_t)slot * 4096;
#pragma unroll
            for (int nn = 0; nn < 8; nn++) {
                int col = nn * 8 + (lane & 3) * 2;
                *(uint32_t*)&pb[r1 * 64 + col] = pack_hi(acc[nn][0], acc[nn][1]);
                *(uint32_t*)&pb[r2 * 64 + col] = pack_hi(acc[nn][2], acc[nn][3]);
            }
            if ((lane & 3) == 0) {
                g_partl[slot * 64 + r1] = ls1;
                g_partl[slot * 64 + r2] = ls2;
            }
        }
    }
}

// ---------------------------------------------------------------------------
// Combine: 128 CTAs (64 groups x 2 slices of 32 rows); bf16 partials,
// each thread sums one 16B chunk (8 bf16) across the 8 slots.
// ---------------------------------------------------------------------------
__global__ __launch_bounds__(256) void combine_kernel()
{
    __shared__ float sinv[32];
    int blk = blockIdx.x;
    int g  = blk >> 1;
    int sl = blk & 1;
    int bh = g >> 2, di = g & 3;
    int qb = (di < 2) ? di : (60 + di);
    int b  = bh >> 3, h = bh & 7;
    int t  = threadIdx.x;

    if (t < 32) {
        int row = sl * 32 + t;
        float L = 0.f;
#pragma unroll
        for (int s = 0; s < 8; s++) L += g_partl[(g * 8 + s) * 64 + row];
        sinv[t] = 1.0f / L;
    }
    __syncthreads();

    int idx8 = sl * 256 + t;            // 16B-chunk index in 64x64 bf16 tile
    int row  = idx8 >> 3;
    int col8 = (idx8 & 7) * 8;
    float o[8];
#pragma unroll
    for (int c = 0; c < 8; c++) o[c] = 0.f;
#pragma unroll
    for (int s = 0; s < 8; s++) {
        uint4 v = *(const uint4*)&g_partb[(size_t)(g * 8 + s) * 4096 + row * 64 + col8];
        float2 a0 = unpk(v.x), a1 = unpk(v.y), a2 = unpk(v.z), a3 = unpk(v.w);
        o[0] += a0.x; o[1] += a0.y; o[2] += a1.x; o[3] += a1.y;
        o[4] += a2.x; o[5] += a2.y; o[6] += a3.x; o[7] += a3.y;
    }
    float inv = sinv[row - sl * 32];
    uint4 pk;
    pk.x = pack_hi(o[0] * inv, o[1] * inv);
    pk.y = pack_hi(o[2] * inv, o[3] * inv);
    pk.z = pack_hi(o[4] * inv, o[5] * inv);
    pk.w = pack_hi(o[6] * inv, o[7] * inv);
    size_t dst = ((size_t)(b * 4096 + qb * 64 + row)) * 512 + h * 64 + col8;
    *(uint4*)&g_xb[dst] = pk;
}

// ---------------------------------------------------------------------------
// LayerNorm (h already includes +bo +x from gemm_wo epilogue)
// ---------------------------------------------------------------------------
__global__ __launch_bounds__(256) void ln_kernel(const float* __restrict__ gamma,
                                                 const float* __restrict__ beta,
                                                 float* __restrict__ out)
{
    int row = blockIdx.x;
    int t = threadIdx.x;
    size_t base = (size_t)row * 512;
    float h0 = g_h[base + t];
    float h1 = g_h[base + t + 256];
    float s = h0 + h1;
    float q = h0*h0 + h1*h1;
#pragma unroll
    for (int m = 16; m >= 1; m >>= 1) {
        s += __shfl_xor_sync(0xffffffffu, s, m);
        q += __shfl_xor_sync(0xffffffffu, q, m);
    }
    __shared__ float ss[8], qq[8];
    int w = t >> 5;
    if ((t & 31) == 0) { ss[w] = s; qq[w] = q; }
    __syncthreads();
    float S2 = 0.f, Q2 = 0.f;
#pragma unroll
    for (int i = 0; i < 8; i++) { S2 += ss[i]; Q2 += qq[i]; }
    float mu  = S2 * (1.0f / 512.0f);
    float var = Q2 * (1.0f / 512.0f) - mu * mu;
    float inv = rsqrtf(var + 1e-12f);
    out[base + t]       = (h0 - mu) * inv * gamma[t]       + beta[t];
    out[base + t + 256] = (h1 - mu) * inv * gamma[t + 256] + beta[t + 256];
}

// ---------------------------------------------------------------------------
extern "C" void kernel_launch(void* const* d_in, const int* in_sizes, int n_in,
                              void* d_out, int out_size)
{
    const float* x     = (const float*)d_in[0];
    const float* mask  = (const float*)d_in[1];
    const int*   rb    = (const int*)  d_in[2];
    const float* Wq    = (const float*)d_in[3];
    const float* Wk    = (const float*)d_in[4];
    const float* Wv    = (const float*)d_in[5];
    const float* Wo    = (const float*)d_in[6];
    const float* bo    = (const float*)d_in[7];
    const float* gamma = (const float*)d_in[8];
    const float* beta  = (const float*)d_in[9];
    float* out = (float*)d_out;

    float* hp;
    __nv_bfloat16 *xb, *wtb;
    cudaGetSymbolAddress((void**)&hp, g_h);
    cudaGetSymbolAddress((void**)&xb, g_xb);
    cudaGetSymbolAddress((void**)&wtb, g_wtb);

    cudaFuncSetAttribute(gemm_wo,  cudaFuncAttributeMaxDynamicSharedMemorySize, GEMM_SMEM);
    cudaFuncSetAttribute(gemm_qkv, cudaFuncAttributeMaxDynamicSharedMemorySize, GEMM_SMEM);
    cudaFuncSetAttribute(attn_hmma, cudaFuncAttributeMaxDynamicSharedMemorySize, ATT_SMEM);

    prep_kernel<<<4096 + 1024, 256>>>(x, xb, Wq, Wk, Wv, Wo, wtb);

    dim3 gq(12, 64);                         // 1536/128 x 8192/128
    gemm_qkv<<<gq, 256, GEMM_SMEM>>>(xb, wtb);

    attn_hmma<<<16 * 92, 256, ATT_SMEM>>>(mask, rb);
    combine_kernel<<<128, 256>>>();

    dim3 go(4, 64);
    gemm_wo<<<go, 256, GEMM_SMEM>>>(xb, wtb + 3*262144, x, bo, hp);

    ln_kernel<<<Bb * Ss, 256>>>(gamma, beta, out);
}

// round 16
// speedup vs baseline: 1.0679x; 1.0347x over previous
#include <cuda_runtime.h>
#include <cuda_bf16.h>
#include <math.h>
#include <stdint.h>

#define Bb 2
#define Ss 4096
#define Dd 512
#define NROWS (Bb*Ss)      // 8192
#define NEGF -1000000000.0f

// ---------------- scratch (device globals: allocation-free) ----------------
__device__ __align__(16) __nv_bfloat16 g_partb[512ULL*4096];  // dense partials bf16
__device__ float g_partl[512*64];                             // dense partial ls
__device__ __align__(16) __nv_bfloat16 g_xb[NROWS*Dd];    // x bf16, later ctx bf16
__device__ __align__(16) __nv_bfloat16 g_wtb[4*Dd*Dd];    // W^T bf16 x4
__device__ __align__(16) __nv_bfloat16 g_qc[16ULL*4096*64];
__device__ __align__(16) __nv_bfloat16 g_kc[16ULL*4096*64];
__device__ __align__(16) __nv_bfloat16 g_vc[16ULL*4096*64];

// ---------------- PTX helpers ----------------
__device__ __forceinline__ uint32_t smem_u32(const void* p) {
    return (uint32_t)__cvta_generic_to_shared(p);
}
#define CPASYNC16(dst, src) \
    asm volatile("cp.async.cg.shared.global [%0], [%1], 16;" :: "r"(dst), "l"(src))
#define CPCOMMIT() asm volatile("cp.async.commit_group;" ::: "memory")
#define CPWAIT(n)  asm volatile("cp.async.wait_group %0;" :: "n"(n) : "memory")

#define LDSM_X4(r0, r1, r2, r3, a) \
    asm volatile("ldmatrix.sync.aligned.m8n8.x4.shared.b16 {%0,%1,%2,%3}, [%4];" \
                 : "=r"(r0), "=r"(r1), "=r"(r2), "=r"(r3) : "r"(a))
#define LDSM_X4T(r0, r1, r2, r3, a) \
    asm volatile("ldmatrix.sync.aligned.m8n8.x4.trans.shared.b16 {%0,%1,%2,%3}, [%4];" \
                 : "=r"(r0), "=r"(r1), "=r"(r2), "=r"(r3) : "r"(a))

#define MMA16816(D, A, B0, B1) \
    asm volatile("mma.sync.aligned.m16n8k16.row.col.f32.bf16.bf16.f32 " \
                 "{%0,%1,%2,%3},{%4,%5,%6,%7},{%8,%9},{%0,%1,%2,%3};" \
                 : "+f"((D)[0]), "+f"((D)[1]), "+f"((D)[2]), "+f"((D)[3]) \
                 : "r"((A)[0]), "r"((A)[1]), "r"((A)[2]), "r"((A)[3]), \
                   "r"(B0), "r"(B1))

__device__ __forceinline__ uint32_t pack_hi(float a, float b) {
    __nv_bfloat162 h = __floats2bfloat162_rn(a, b);
    return *(uint32_t*)&h;
}
__device__ __forceinline__ float2 unpk(uint32_t u) {
    __nv_bfloat162 h = *(__nv_bfloat162*)&u;
    return make_float2(__bfloat162float(h.x), __bfloat162float(h.y));
}

// ---------------------------------------------------------------------------
// Fused prep: x -> bf16 (CTAs 0..4095) and 4x W -> W^T bf16 (CTAs 4096..5119)
// ---------------------------------------------------------------------------
__global__ __launch_bounds__(256) void prep_kernel(
    const float* __restrict__ X, __nv_bfloat16* __restrict__ Xb,
    const float* __restrict__ W0, const float* __restrict__ W1,
    const float* __restrict__ W2, const float* __restrict__ W3,
    __nv_bfloat16* __restrict__ Th)
{
    int cb = blockIdx.x;
    int t = threadIdx.x;
    if (cb < 4096) {
        size_t i0 = (size_t)cb * 1024 + t * 2;
        float2 v0 = *(const float2*)&X[i0];
        float2 v1 = *(const float2*)&X[i0 + 512];
        *(uint32_t*)&Xb[i0]       = pack_hi(v0.x, v0.y);
        *(uint32_t*)&Xb[i0 + 512] = pack_hi(v1.x, v1.y);
        return;
    }
    __shared__ float tile[32][33];
    int idx = cb - 4096;
    int z = idx >> 8;
    int rest = idx & 255;
    const float* W = (z == 0) ? W0 : (z == 1) ? W1 : (z == 2) ? W2 : W3;
    __nv_bfloat16* th = Th + (size_t)z * 262144;
    int n0 = (rest & 15) * 32, k0 = (rest >> 4) * 32;
    int tx = t & 31, ty = t >> 5;
#pragma unroll
    for (int j = 0; j < 32; j += 8)
        tile[ty + j][tx] = W[(size_t)(k0 + ty + j) * 512 + n0 + tx];
    __syncthreads();
#pragma unroll
    for (int j = 0; j < 32; j += 8) {
        int row = ty + j;
        th[(size_t)(n0 + row) * 512 + k0 + tx] = __float2bfloat16(tile[tx][row]);
    }
}

// ---------------------------------------------------------------------------
// QKV GEMM (CTA 128x128, BK=64, dbl buf) -> per-head bf16 [bh][s][64]
// ---------------------------------------------------------------------------
#define GEMM_SMEM 65536

__device__ __forceinline__ void gemm_ld_chunk(const __nv_bfloat16* __restrict__ A,
                                              const __nv_bfloat16* __restrict__ Bt,
                                              int rowBase, int colBase, int k0,
                                              uint32_t Ab, uint32_t Bbuf, int t)
{
#pragma unroll
    for (int it = 0; it < 4; it++) {
        int idx = it * 256 + t;
        int r = idx >> 3, c = idx & 7;
        uint32_t d = Ab + r * 128 + ((c ^ (r & 7)) << 4);
        CPASYNC16(d, &A[(size_t)(rowBase + r) * 512 + k0 + c * 8]);
    }
#pragma unroll
    for (int it = 0; it < 4; it++) {
        int idx = it * 256 + t;
        int r = idx >> 3, c = idx & 7;
        uint32_t d = Bbuf + r * 128 + ((c ^ (r & 7)) << 4);
        CPASYNC16(d, &Bt[(size_t)(colBase + r) * 512 + k0 + c * 8]);
    }
    CPCOMMIT();
}

__global__ __launch_bounds__(256, 2)
void gemm_qkv(const __nv_bfloat16* __restrict__ A,
              const __nv_bfloat16* __restrict__ Bt)
{
    extern __shared__ __align__(128) char sm[];
    uint32_t sbase = smem_u32(sm);
    int t = threadIdx.x, w = t >> 5, lane = t & 31;
    int rowBase = blockIdx.y * 128, colBase = blockIdx.x * 128;
    int wm = (w & 3) * 32, wn = (w >> 2) * 64;
    int laneA_row = (((lane >> 3) & 1) << 3) + (lane & 7);
    int laneA_ch  = (lane >> 4);
    int laneB_row = ((lane >> 4) << 3) + (lane & 7);
    int laneB_ch  = ((lane >> 3) & 1);

    float acc[2][8][4];
#pragma unroll
    for (int mt = 0; mt < 2; mt++)
#pragma unroll
        for (int nt = 0; nt < 8; nt++)
#pragma unroll
            for (int e = 0; e < 4; e++) acc[mt][nt][e] = 0.f;

    gemm_ld_chunk(A, Bt, rowBase, colBase, 0, sbase, sbase + 16384u, t);

    for (int i = 0; i < 8; i++) {
        int buf = i & 1;
        if (i < 7) {
            uint32_t Ab = sbase + (buf ? 0u : 32768u);
            gemm_ld_chunk(A, Bt, rowBase, colBase, (i + 1) * 64, Ab, Ab + 16384u, t);
            CPWAIT(1);
        } else {
            CPWAIT(0);
        }
        __syncthreads();

        uint32_t Ab = sbase + (buf ? 32768u : 0u);
        uint32_t Bbuf = Ab + 16384u;
#pragma unroll
        for (int ks = 0; ks < 4; ks++) {
            uint32_t afr[2][4];
#pragma unroll
            for (int mt = 0; mt < 2; mt++) {
                int row = wm + mt * 16 + laneA_row;
                int ch  = ks * 2 + laneA_ch;
                uint32_t a = Ab + row * 128 + ((ch ^ (row & 7)) << 4);
                LDSM_X4(afr[mt][0], afr[mt][1], afr[mt][2], afr[mt][3], a);
            }
#pragma unroll
            for (int p = 0; p < 4; p++) {
                int row = wn + p * 16 + laneB_row;
                int ch  = ks * 2 + laneB_ch;
                uint32_t a = Bbuf + row * 128 + ((ch ^ (row & 7)) << 4);
                uint32_t b0, b1, b2, b3;
                LDSM_X4(b0, b1, b2, b3, a);
#pragma unroll
                for (int mt = 0; mt < 2; mt++) {
                    MMA16816(acc[mt][p*2],   afr[mt], b0, b1);
                    MMA16816(acc[mt][p*2+1], afr[mt], b2, b3);
                }
            }
        }
        __syncthreads();
    }

    int tensor = colBase >> 9;
    float alpha = (tensor == 0) ? 0.125f : 1.0f;
    __nv_bfloat16* dst = (tensor == 0) ? g_qc : (tensor == 1) ? g_kc : g_vc;

#pragma unroll
    for (int mt = 0; mt < 2; mt++)
#pragma unroll
        for (int nt = 0; nt < 8; nt++) {
            float* a4 = acc[mt][nt];
            int r0 = rowBase + wm + mt * 16 + (lane >> 2);
            int cc = (colBase & 511) + wn + nt * 8 + (lane & 3) * 2;
            int hh = cc >> 6, dd = cc & 63;
            int b = r0 >> 12, s = r0 & 4095;
            size_t off = ((size_t)((b << 3) + hh) * 4096 + s) * 64 + dd;
            *(uint32_t*)&dst[off] = pack_hi(a4[0]*alpha, a4[1]*alpha);
            *(uint32_t*)&dst[off + 8ULL*64] = pack_hi(a4[2]*alpha, a4[3]*alpha);
        }
}

// ---------------------------------------------------------------------------
// Fused Wo GEMM + residual + bias + LayerNorm -> out.
// CTA tile M=32 x N=512, BK=32 double-buffered, grid 256, 8 warps (n-split 64).
// smem: A0 0 | A1 2048 | B0 4096 | B1 36864 | lnS 69632 | lnQ 70656 |
//       lnM 71680 | lnI 71808  (total 71936)
// ---------------------------------------------------------------------------
#define WO_SMEM 71936

__device__ __forceinline__ void wo_ld_chunk(const __nv_bfloat16* __restrict__ A,
                                            const __nv_bfloat16* __restrict__ Bt,
                                            int rowBase, int k0,
                                            uint32_t Ab, uint32_t Bbuf, int t)
{
    if (t < 128) {
        int r = t >> 2, c = t & 3;
        CPASYNC16(Ab + r * 64 + ((c ^ ((r >> 1) & 3)) << 4),
                  &A[(size_t)(rowBase + r) * 512 + k0 + c * 8]);
    }
#pragma unroll
    for (int it = 0; it < 8; it++) {
        int idx = it * 256 + t;
        int r = idx >> 2, c = idx & 3;
        CPASYNC16(Bbuf + r * 64 + ((c ^ ((r >> 1) & 3)) << 4),
                  &Bt[(size_t)r * 512 + k0 + c * 8]);
    }
    CPCOMMIT();
}

__global__ __launch_bounds__(256, 2)
void gemm_wo_ln(const __nv_bfloat16* __restrict__ A,
                const __nv_bfloat16* __restrict__ Bt,
                const float* __restrict__ X,
                const float* __restrict__ bo2,
                const float* __restrict__ gamma,
                const float* __restrict__ beta,
                float* __restrict__ out)
{
    extern __shared__ __align__(128) char sm[];
    uint32_t sb = smem_u32(sm);
    float* lnS = (float*)(sm + 69632);   // [8][32]
    float* lnQ = (float*)(sm + 70656);   // [8][32]
    float* lnM = (float*)(sm + 71680);   // [32]
    float* lnI = (float*)(sm + 71808);   // [32]

    int t = threadIdx.x, w = t >> 5, lane = t & 31;
    int rowBase = blockIdx.x * 32;
    int laneA_row = (((lane >> 3) & 1) << 3) + (lane & 7);
    int laneA_ch  = (lane >> 4);
    int laneB_row = ((lane >> 4) << 3) + (lane & 7);
    int laneB_ch  = ((lane >> 3) & 1);

    float acc[2][8][4];
#pragma unroll
    for (int mt = 0; mt < 2; mt++)
#pragma unroll
        for (int nt = 0; nt < 8; nt++)
#pragma unroll
            for (int e = 0; e < 4; e++) acc[mt][nt][e] = 0.f;

    wo_ld_chunk(A, Bt, rowBase, 0, sb, sb + 4096u, t);

    for (int i = 0; i < 16; i++) {
        int buf = i & 1;
        if (i < 15) {
            uint32_t Ab = sb + (buf ? 0u : 2048u);
            uint32_t Bbuf = sb + 4096u + (buf ? 0u : 32768u);
            wo_ld_chunk(A, Bt, rowBase, (i + 1) * 32, Ab, Bbuf, t);
            CPWAIT(1);
        } else {
            CPWAIT(0);
        }
        __syncthreads();

        uint32_t Ab = sb + (buf ? 2048u : 0u);
        uint32_t Bbuf = sb + 4096u + (buf ? 32768u : 0u);
#pragma unroll
        for (int ks = 0; ks < 2; ks++) {
            uint32_t afr[2][4];
#pragma unroll
            for (int mt = 0; mt < 2; mt++) {
                int row = mt * 16 + laneA_row;
                int ch  = ks * 2 + laneA_ch;
                LDSM_X4(afr[mt][0], afr[mt][1], afr[mt][2], afr[mt][3],
                        Ab + row * 64 + ((ch ^ ((row >> 1) & 3)) << 4));
            }
#pragma unroll
            for (int p = 0; p < 4; p++) {
                int row = w * 64 + p * 16 + laneB_row;
                int ch  = ks * 2 + laneB_ch;
                uint32_t b0, b1, b2, b3;
                LDSM_X4(b0, b1, b2, b3,
                        Bbuf + row * 64 + ((ch ^ ((row >> 1) & 3)) << 4));
#pragma unroll
                for (int mt = 0; mt < 2; mt++) {
                    MMA16816(acc[mt][p*2],   afr[mt], b0, b1);
                    MMA16816(acc[mt][p*2+1], afr[mt], b2, b3);
                }
            }
        }
        __syncthreads();
    }

    // ---- epilogue: h = acc + bo + x; LN stats; write out ----
    int rq = lane >> 2;
#pragma unroll
    for (int s = 0; s < 4; s++) {
        int mt = s >> 1, hi = (s & 1) * 2;
        int grow = rowBase + s * 8 + rq;
        float ssum = 0.f, qsum = 0.f;
#pragma unroll
        for (int nt = 0; nt < 8; nt++) {
            int col = w * 64 + nt * 8 + (lane & 3) * 2;
            float2 bv = *(const float2*)&bo2[col];
            float2 xv = *(const float2*)&X[(size_t)grow * 512 + col];
            float h0 = acc[mt][nt][hi]     + bv.x + xv.x;
            float h1 = acc[mt][nt][hi + 1] + bv.y + xv.y;
            acc[mt][nt][hi] = h0; acc[mt][nt][hi + 1] = h1;
            ssum += h0 + h1;
            qsum += h0 * h0 + h1 * h1;
        }
        ssum += __shfl_xor_sync(0xffffffffu, ssum, 1);
        ssum += __shfl_xor_sync(0xffffffffu, ssum, 2);
        qsum += __shfl_xor_sync(0xffffffffu, qsum, 1);
        qsum += __shfl_xor_sync(0xffffffffu, qsum, 2);
        if ((lane & 3) == 0) {
            lnS[w * 32 + s * 8 + rq] = ssum;
            lnQ[w * 32 + s * 8 + rq] = qsum;
        }
    }
    __syncthreads();
    if (t < 32) {
        float S = 0.f, Q = 0.f;
#pragma unroll
        for (int w8 = 0; w8 < 8; w8++) { S += lnS[w8 * 32 + t]; Q += lnQ[w8 * 32 + t]; }
        float mu  = S * (1.0f / 512.0f);
        float var = Q * (1.0f / 512.0f) - mu * mu;
        lnM[t] = mu;
        lnI[t] = rsqrtf(var + 1e-12f);
    }
    __syncthreads();

#pragma unroll
    for (int s = 0; s < 4; s++) {
        int mt = s >> 1, hi = (s & 1) * 2;
        int lrow = s * 8 + rq;
        float mu = lnM[lrow], inv = lnI[lrow];
        size_t grow = rowBase + lrow;
#pragma unroll
        for (int nt = 0; nt < 8; nt++) {
            int col = w * 64 + nt * 8 + (lane & 3) * 2;
            float2 gv = *(const float2*)&gamma[col];
            float2 bv = *(const float2*)&beta[col];
            float o0 = (acc[mt][nt][hi]     - mu) * inv * gv.x + bv.x;
            float o1 = (acc[mt][nt][hi + 1] - mu) * inv * gv.y + bv.y;
            *(float2*)&out[grow * 512 + col] = make_float2(o0, o1);
        }
    }
}

// ---------------------------------------------------------------------------
// HMMA attention (best-known config): 2-stage ring, hoisted Q, (256,2).
// ---------------------------------------------------------------------------
#define OFF_KS 8192
#define OFF_VS 24576
#define OFF_EX 40960
#define EX_PITCH 66
#define OFF_KM 57856
#define OFF_RL 58368
#define ATT_SMEM 58880

__device__ __forceinline__ int kb_of(bool mid, int qb, int chunk, int itk,
                                     const int* __restrict__ rand_blocks)
{
    if (!mid) return chunk * 8 + itk;
    if (itk < 3) return qb - 1 + itk;
    if (itk == 3) return 0;
    if (itk == 4) return 63;
    return rand_blocks[(qb - 2) * 3 + (itk - 5)];
}

__device__ __forceinline__ void attn_prefetch_kv(int bh, int kb, uint32_t KSb,
                                                 uint32_t VSb, int t)
{
    size_t koff = ((size_t)bh * 4096 + kb * 64) * 64;
#pragma unroll
    for (int it = 0; it < 2; it++) {
        int idx = it * 256 + t;
        int r = idx >> 3, c = idx & 7;
        CPASYNC16(KSb + r * 128 + ((c ^ (r & 7)) << 4), &g_kc[koff + r * 64 + c * 8]);
    }
#pragma unroll
    for (int it = 0; it < 2; it++) {
        int idx = it * 256 + t;
        int r = idx >> 3, c = idx & 7;
        CPASYNC16(VSb + r * 128 + ((c ^ (r & 7)) << 4), &g_vc[koff + r * 64 + c * 8]);
    }
    CPCOMMIT();
}

__global__ __launch_bounds__(256, 2)
void attn_hmma(const float* __restrict__ mask, const int* __restrict__ rand_blocks)
{
    extern __shared__ __align__(128) char sm[];
    uint32_t sb = smem_u32(sm);
    const uint32_t QS = sb;
    float* km   = (float*)(sm + OFF_KM);    // [2][64]
    float* redL = (float*)(sm + OFF_RL);
    float* ex   = (float*)(sm + OFF_EX);    // [64][EX_PITCH]

    int t = threadIdx.x, w = t >> 5, lane = t & 31;
    int wm = (w & 3) * 16;
    int wni = w >> 2;
    int wn  = wni * 32;

    int u  = blockIdx.x % 92;
    int bh = blockIdx.x / 92;
    int b  = bh >> 3, h = bh & 7;

    bool mid = (u < 60);
    int qb, chunk = 0, di = 0;
    if (mid) { qb = u + 2; }
    else {
        int d = u - 60;
        di = d >> 3; chunk = d & 7;
        qb = (di < 2) ? di : (60 + di);
    }

    // ---- prologue: Q + K0/V0 via cp.async (one group), km[0] ----
    {
        size_t qoff = ((size_t)bh * 4096 + qb * 64) * 64;
#pragma unroll
        for (int it = 0; it < 2; it++) {
            int idx = it * 256 + t;
            int r = idx >> 3, c = idx & 7;
            CPASYNC16(QS + r * 128 + ((c ^ (r & 7)) << 4), &g_qc[qoff + r * 64 + c * 8]);
        }
        int kb0 = kb_of(mid, qb, chunk, 0, rand_blocks);
        attn_prefetch_kv(bh, kb0, sb + OFF_KS, sb + OFF_VS, t);
        if (t < 64) km[t] = mask[b * 4096 + kb0 * 64 + t];
    }

    int r1 = wm + (lane >> 2), r2 = r1 + 8;
    float mq1 = mask[b * 4096 + qb * 64 + r1];
    float mq2 = mask[b * 4096 + qb * 64 + r2];

    float acc[8][4];
#pragma unroll
    for (int nn = 0; nn < 8; nn++)
#pragma unroll
        for (int e = 0; e < 4; e++) acc[nn][e] = 0.f;
    float ls1 = 0.f, ls2 = 0.f;

    int laneA_row = (((lane >> 3) & 1) << 3) + (lane & 7);
    int laneA_ch  = lane >> 4;
    int laneB_row = ((lane >> 4) << 3) + (lane & 7);
    int laneB_ch  = (lane >> 3) & 1;
    int laneV_row = lane & 15;
    int laneV_g   = lane >> 4;

    uint32_t qh[4][4];

    for (int itk = 0; itk < 8; itk++) {
        int buf = itk & 1;
        bool band = mid && (itk < 3);

        __syncthreads();
        if (itk < 7) {
            int kbn = kb_of(mid, qb, chunk, itk + 1, rand_blocks);
            attn_prefetch_kv(bh, kbn, sb + OFF_KS + (buf ^ 1) * 8192,
                             sb + OFF_VS + (buf ^ 1) * 8192, t);
            if (t < 64) km[(buf ^ 1) * 64 + t] = mask[b * 4096 + kbn * 64 + t];
            CPWAIT(1);
        } else {
            CPWAIT(0);
        }
        __syncthreads();

        if (itk == 0) {
            int row = wm + laneA_row;
#pragma unroll
            for (int ks = 0; ks < 4; ks++) {
                int ch = ks * 2 + laneA_ch;
                LDSM_X4(qh[ks][0], qh[ks][1], qh[ks][2], qh[ks][3],
                        QS + row * 128 + ((ch ^ (row & 7)) << 4));
            }
        }

        uint32_t KSb = sb + OFF_KS + buf * 8192;
        uint32_t VSb = sb + OFF_VS + buf * 8192;
        const float* kmask_s = km + buf * 64;

        // ---- QK ----
        float sc[4][4];
#pragma unroll
        for (int nt = 0; nt < 4; nt++)
#pragma unroll
            for (int e = 0; e < 4; e++) sc[nt][e] = 0.f;

#pragma unroll
        for (int ks = 0; ks < 4; ks++) {
            int kc2 = ks * 2;
#pragma unroll
            for (int g = 0; g < 2; g++) {
                uint32_t kh[4];
                int row = wn + g * 16 + laneB_row;
                int ch = kc2 + laneB_ch;
                LDSM_X4(kh[0], kh[1], kh[2], kh[3],
                        KSb + row * 128 + ((ch ^ (row & 7)) << 4));
                MMA16816(sc[g*2],   qh[ks], kh[0], kh[1]);
                MMA16816(sc[g*2+1], qh[ks], kh[2], kh[3]);
            }
        }

        // ---- mask ----
#pragma unroll
        for (int nt = 0; nt < 4; nt++) {
            int col = wn + nt * 8 + (lane & 3) * 2;
            float mk0 = kmask_s[col], mk1 = kmask_s[col + 1];
            float m00 = band ? mk0 * mq1 : mk0;
            float m01 = band ? mk1 * mq1 : mk1;
            float m10 = band ? mk0 * mq2 : mk0;
            float m11 = band ? mk1 * mq2 : mk1;
            sc[nt][0] += (1.0f - m00) * NEGF;
            sc[nt][1] += (1.0f - m01) * NEGF;
            sc[nt][2] += (1.0f - m10) * NEGF;
            sc[nt][3] += (1.0f - m11) * NEGF;
        }

        // ---- exp + bf16 pack ----
        uint32_t aph[2][4];
#pragma unroll
        for (int nt = 0; nt < 4; nt++) {
            float p00 = __expf(sc[nt][0]), p01 = __expf(sc[nt][1]);
            float p10 = __expf(sc[nt][2]), p11 = __expf(sc[nt][3]);
            ls1 += p00 + p01; ls2 += p10 + p11;
            int j = nt >> 1, hf = (nt & 1) * 2;
            aph[j][hf]     = pack_hi(p00, p01);
            aph[j][hf + 1] = pack_hi(p10, p11);
        }

        // ---- PV ----
#pragma unroll
        for (int j = 0; j < 2; j++) {
            int vrow = wn + j * 16 + laneV_row;
            uint32_t vbase = VSb + vrow * 128;
            int sw = (vrow & 7) << 4;
#pragma unroll
            for (int np = 0; np < 4; np++) {
                uint32_t vh4[4];
                int ch = np * 2 + laneV_g;
                LDSM_X4T(vh4[0], vh4[1], vh4[2], vh4[3], vbase + ((ch << 4) ^ sw));
                MMA16816(acc[np*2],   aph[j], vh4[0], vh4[1]);
                MMA16816(acc[np*2+1], aph[j], vh4[2], vh4[3]);
            }
        }
    }

    // ---- final ls combine ----
    ls1 += __shfl_xor_sync(0xffffffffu, ls1, 1);
    ls1 += __shfl_xor_sync(0xffffffffu, ls1, 2);
    ls2 += __shfl_xor_sync(0xffffffffu, ls2, 1);
    ls2 += __shfl_xor_sync(0xffffffffu, ls2, 2);
    if ((lane & 3) == 0) {
        redL[wni * 64 + r1] = ls1;
        redL[wni * 64 + r2] = ls2;
    }
    __syncthreads();
    ls1 = redL[r1] + redL[64 + r1];
    ls2 = redL[r2] + redL[64 + r2];

    // ---- cross-half acc reduction ----
    if (wni == 1) {
#pragma unroll
        for (int nn = 0; nn < 8; nn++) {
            int col = nn * 8 + (lane & 3) * 2;
            *(float2*)&ex[r1 * EX_PITCH + col] = make_float2(acc[nn][0], acc[nn][1]);
            *(float2*)&ex[r2 * EX_PITCH + col] = make_float2(acc[nn][2], acc[nn][3]);
        }
    }
    __syncthreads();
    if (wni == 0) {
#pragma unroll
        for (int nn = 0; nn < 8; nn++) {
            int col = nn * 8 + (lane & 3) * 2;
            float2 v1 = *(float2*)&ex[r1 * EX_PITCH + col];
            float2 v2 = *(float2*)&ex[r2 * EX_PITCH + col];
            acc[nn][0] += v1.x; acc[nn][1] += v1.y;
            acc[nn][2] += v2.x; acc[nn][3] += v2.y;
        }

        if (mid) {
            float inv1 = 1.0f / ls1, inv2 = 1.0f / ls2;
#pragma unroll
            for (int nn = 0; nn < 8; nn++) {
                int col = nn * 8 + (lane & 3) * 2;
                size_t o1 = ((size_t)(b * 4096 + qb * 64 + r1)) * 512 + h * 64 + col;
                size_t o2 = ((size_t)(b * 4096 + qb * 64 + r2)) * 512 + h * 64 + col;
                *(uint32_t*)&g_xb[o1] = pack_hi(acc[nn][0] * inv1, acc[nn][1] * inv1);
                *(uint32_t*)&g_xb[o2] = pack_hi(acc[nn][2] * inv2, acc[nn][3] * inv2);
            }
        } else {
            int slot = (bh * 4 + di) * 8 + chunk;
            __nv_bfloat16* pb = g_partb + (size_t)slot * 4096;
#pragma unroll
            for (int nn = 0; nn < 8; nn++) {
                int col = nn * 8 + (lane & 3) * 2;
                *(uint32_t*)&pb[r1 * 64 + col] = pack_hi(acc[nn][0], acc[nn][1]);
                *(uint32_t*)&pb[r2 * 64 + col] = pack_hi(acc[nn][2], acc[nn][3]);
            }
            if ((lane & 3) == 0) {
                g_partl[slot * 64 + r1] = ls1;
                g_partl[slot * 64 + r2] = ls2;
            }
        }
    }
}

// ---------------------------------------------------------------------------
// Combine: 128 CTAs (64 groups x 2 slices of 32 rows); bf16 partials.
// ---------------------------------------------------------------------------
__global__ __launch_bounds__(256) void combine_kernel()
{
    __shared__ float sinv[32];
    int blk = blockIdx.x;
    int g  = blk >> 1;
    int sl = blk & 1;
    int bh = g >> 2, di = g & 3;
    int qb = (di < 2) ? di : (60 + di);
    int b  = bh >> 3, h = bh & 7;
    int t  = threadIdx.x;

    if (t < 32) {
        int row = sl * 32 + t;
        float L = 0.f;
#pragma unroll
        for (int s = 0; s < 8; s++) L += g_partl[(g * 8 + s) * 64 + row];
        sinv[t] = 1.0f / L;
    }
    __syncthreads();

    int idx8 = sl * 256 + t;
    int row  = idx8 >> 3;
    int col8 = (idx8 & 7) * 8;
    float o[8];
#pragma unroll
    for (int c = 0; c < 8; c++) o[c] = 0.f;
#pragma unroll
    for (int s = 0; s < 8; s++) {
        uint4 v = *(const uint4*)&g_partb[(size_t)(g * 8 + s) * 4096 + row * 64 + col8];
        float2 a0 = unpk(v.x), a1 = unpk(v.y), a2 = unpk(v.z), a3 = unpk(v.w);
        o[0] += a0.x; o[1] += a0.y; o[2] += a1.x; o[3] += a1.y;
        o[4] += a2.x; o[5] += a2.y; o[6] += a3.x; o[7] += a3.y;
    }
    float inv = sinv[row - sl * 32];
    uint4 pk;
    pk.x = pack_hi(o[0] * inv, o[1] * inv);
    pk.y = pack_hi(o[2] * inv, o[3] * inv);
    pk.z = pack_hi(o[4] * inv, o[5] * inv);
    pk.w = pack_hi(o[6] * inv, o[7] * inv);
    size_t dst = ((size_t)(b * 4096 + qb * 64 + row)) * 512 + h * 64 + col8;
    *(uint4*)&g_xb[dst] = pk;
}

// ---------------------------------------------------------------------------
extern "C" void kernel_launch(void* const* d_in, const int* in_sizes, int n_in,
                              void* d_out, int out_size)
{
    const float* x     = (const float*)d_in[0];
    const float* mask  = (const float*)d_in[1];
    const int*   rb    = (const int*)  d_in[2];
    const float* Wq    = (const float*)d_in[3];
    const float* Wk    = (const float*)d_in[4];
    const float* Wv    = (const float*)d_in[5];
    const float* Wo    = (const float*)d_in[6];
    const float* bo    = (const float*)d_in[7];
    const float* gamma = (const float*)d_in[8];
    const float* beta  = (const float*)d_in[9];
    float* out = (float*)d_out;

    __nv_bfloat16 *xb, *wtb;
    cudaGetSymbolAddress((void**)&xb, g_xb);
    cudaGetSymbolAddress((void**)&wtb, g_wtb);

    cudaFuncSetAttribute(gemm_wo_ln, cudaFuncAttributeMaxDynamicSharedMemorySize, WO_SMEM);
    cudaFuncSetAttribute(gemm_qkv,  cudaFuncAttributeMaxDynamicSharedMemorySize, GEMM_SMEM);
    cudaFuncSetAttribute(attn_hmma, cudaFuncAttributeMaxDynamicSharedMemorySize, ATT_SMEM);

    prep_kernel<<<4096 + 1024, 256>>>(x, xb, Wq, Wk, Wv, Wo, wtb);

    dim3 gq(12, 64);                         // 1536/128 x 8192/128
    gemm_qkv<<<gq, 256, GEMM_SMEM>>>(xb, wtb);

    attn_hmma<<<16 * 92, 256, ATT_SMEM>>>(mask, rb);
    combine_kernel<<<128, 256>>>();

    gemm_wo_ln<<<256, 256, WO_SMEM>>>(xb, wtb + 3*262144, x, bo, gamma, beta, out);
}

// round 17
// speedup vs baseline: 1.0785x; 1.0098x over previous
#include <cuda_runtime.h>
#include <cuda_bf16.h>
#include <math.h>
#include <stdint.h>

#define Bb 2
#define Ss 4096
#define Dd 512
#define NROWS (Bb*Ss)      // 8192
#define NEGF -1000000000.0f

// ---------------- scratch (device globals: allocation-free) ----------------
__device__ __align__(16) __nv_bfloat16 g_partb[512ULL*4096];  // dense partials bf16
__device__ float g_partl[512*64];                             // dense partial ls
__device__ __align__(16) __nv_bfloat16 g_xb[NROWS*Dd];    // x bf16, later ctx bf16
__device__ __align__(16) __nv_bfloat16 g_wtb[4*Dd*Dd];    // W^T bf16 x4
__device__ __align__(16) __nv_bfloat16 g_qc[16ULL*4096*64];
__device__ __align__(16) __nv_bfloat16 g_kc[16ULL*4096*64];
__device__ __align__(16) __nv_bfloat16 g_vc[16ULL*4096*64];

// ---------------- PTX helpers ----------------
__device__ __forceinline__ uint32_t smem_u32(const void* p) {
    return (uint32_t)__cvta_generic_to_shared(p);
}
#define CPASYNC16(dst, src) \
    asm volatile("cp.async.cg.shared.global [%0], [%1], 16;" :: "r"(dst), "l"(src))
#define CPCOMMIT() asm volatile("cp.async.commit_group;" ::: "memory")
#define CPWAIT(n)  asm volatile("cp.async.wait_group %0;" :: "n"(n) : "memory")

#define LDSM_X4(r0, r1, r2, r3, a) \
    asm volatile("ldmatrix.sync.aligned.m8n8.x4.shared.b16 {%0,%1,%2,%3}, [%4];" \
                 : "=r"(r0), "=r"(r1), "=r"(r2), "=r"(r3) : "r"(a))
#define LDSM_X4T(r0, r1, r2, r3, a) \
    asm volatile("ldmatrix.sync.aligned.m8n8.x4.trans.shared.b16 {%0,%1,%2,%3}, [%4];" \
                 : "=r"(r0), "=r"(r1), "=r"(r2), "=r"(r3) : "r"(a))

#define MMA16816(D, A, B0, B1) \
    asm volatile("mma.sync.aligned.m16n8k16.row.col.f32.bf16.bf16.f32 " \
                 "{%0,%1,%2,%3},{%4,%5,%6,%7},{%8,%9},{%0,%1,%2,%3};" \
                 : "+f"((D)[0]), "+f"((D)[1]), "+f"((D)[2]), "+f"((D)[3]) \
                 : "r"((A)[0]), "r"((A)[1]), "r"((A)[2]), "r"((A)[3]), \
                   "r"(B0), "r"(B1))

__device__ __forceinline__ uint32_t pack_hi(float a, float b) {
    __nv_bfloat162 h = __floats2bfloat162_rn(a, b);
    return *(uint32_t*)&h;
}
__device__ __forceinline__ float2 unpk(uint32_t u) {
    __nv_bfloat162 h = *(__nv_bfloat162*)&u;
    return make_float2(__bfloat162float(h.x), __bfloat162float(h.y));
}

// ---------------------------------------------------------------------------
// Fused prep: x -> bf16 (CTAs 0..4095) and 4x W -> W^T bf16 (CTAs 4096..5119)
// ---------------------------------------------------------------------------
__global__ __launch_bounds__(256) void prep_kernel(
    const float* __restrict__ X, __nv_bfloat16* __restrict__ Xb,
    const float* __restrict__ W0, const float* __restrict__ W1,
    const float* __restrict__ W2, const float* __restrict__ W3,
    __nv_bfloat16* __restrict__ Th)
{
    int cb = blockIdx.x;
    int t = threadIdx.x;
    if (cb < 4096) {
        size_t i0 = (size_t)cb * 1024 + t * 2;
        float2 v0 = *(const float2*)&X[i0];
        float2 v1 = *(const float2*)&X[i0 + 512];
        *(uint32_t*)&Xb[i0]       = pack_hi(v0.x, v0.y);
        *(uint32_t*)&Xb[i0 + 512] = pack_hi(v1.x, v1.y);
        return;
    }
    __shared__ float tile[32][33];
    int idx = cb - 4096;
    int z = idx >> 8;
    int rest = idx & 255;
    const float* W = (z == 0) ? W0 : (z == 1) ? W1 : (z == 2) ? W2 : W3;
    __nv_bfloat16* th = Th + (size_t)z * 262144;
    int n0 = (rest & 15) * 32, k0 = (rest >> 4) * 32;
    int tx = t & 31, ty = t >> 5;
#pragma unroll
    for (int j = 0; j < 32; j += 8)
        tile[ty + j][tx] = W[(size_t)(k0 + ty + j) * 512 + n0 + tx];
    __syncthreads();
#pragma unroll
    for (int j = 0; j < 32; j += 8) {
        int row = ty + j;
        th[(size_t)(n0 + row) * 512 + k0 + tx] = __float2bfloat16(tile[tx][row]);
    }
}

// ---------------------------------------------------------------------------
// QKV GEMM (CTA 128x128, BK=64, dbl buf) -> per-head bf16 [bh][s][64]
// ---------------------------------------------------------------------------
#define GEMM_SMEM 65536

__device__ __forceinline__ void gemm_ld_chunk(const __nv_bfloat16* __restrict__ A,
                                              const __nv_bfloat16* __restrict__ Bt,
                                              int rowBase, int colBase, int k0,
                                              uint32_t Ab, uint32_t Bbuf, int t)
{
#pragma unroll
    for (int it = 0; it < 4; it++) {
        int idx = it * 256 + t;
        int r = idx >> 3, c = idx & 7;
        uint32_t d = Ab + r * 128 + ((c ^ (r & 7)) << 4);
        CPASYNC16(d, &A[(size_t)(rowBase + r) * 512 + k0 + c * 8]);
    }
#pragma unroll
    for (int it = 0; it < 4; it++) {
        int idx = it * 256 + t;
        int r = idx >> 3, c = idx & 7;
        uint32_t d = Bbuf + r * 128 + ((c ^ (r & 7)) << 4);
        CPASYNC16(d, &Bt[(size_t)(colBase + r) * 512 + k0 + c * 8]);
    }
    CPCOMMIT();
}

__global__ __launch_bounds__(256, 2)
void gemm_qkv(const __nv_bfloat16* __restrict__ A,
              const __nv_bfloat16* __restrict__ Bt)
{
    extern __shared__ __align__(128) char sm[];
    uint32_t sbase = smem_u32(sm);
    int t = threadIdx.x, w = t >> 5, lane = t & 31;
    int rowBase = blockIdx.y * 128, colBase = blockIdx.x * 128;
    int wm = (w & 3) * 32, wn = (w >> 2) * 64;
    int laneA_row = (((lane >> 3) & 1) << 3) + (lane & 7);
    int laneA_ch  = (lane >> 4);
    int laneB_row = ((lane >> 4) << 3) + (lane & 7);
    int laneB_ch  = ((lane >> 3) & 1);

    float acc[2][8][4];
#pragma unroll
    for (int mt = 0; mt < 2; mt++)
#pragma unroll
        for (int nt = 0; nt < 8; nt++)
#pragma unroll
            for (int e = 0; e < 4; e++) acc[mt][nt][e] = 0.f;

    gemm_ld_chunk(A, Bt, rowBase, colBase, 0, sbase, sbase + 16384u, t);

    for (int i = 0; i < 8; i++) {
        int buf = i & 1;
        if (i < 7) {
            uint32_t Ab = sbase + (buf ? 0u : 32768u);
            gemm_ld_chunk(A, Bt, rowBase, colBase, (i + 1) * 64, Ab, Ab + 16384u, t);
            CPWAIT(1);
        } else {
            CPWAIT(0);
        }
        __syncthreads();

        uint32_t Ab = sbase + (buf ? 32768u : 0u);
        uint32_t Bbuf = Ab + 16384u;
#pragma unroll
        for (int ks = 0; ks < 4; ks++) {
            uint32_t afr[2][4];
#pragma unroll
            for (int mt = 0; mt < 2; mt++) {
                int row = wm + mt * 16 + laneA_row;
                int ch  = ks * 2 + laneA_ch;
                uint32_t a = Ab + row * 128 + ((ch ^ (row & 7)) << 4);
                LDSM_X4(afr[mt][0], afr[mt][1], afr[mt][2], afr[mt][3], a);
            }
#pragma unroll
            for (int p = 0; p < 4; p++) {
                int row = wn + p * 16 + laneB_row;
                int ch  = ks * 2 + laneB_ch;
                uint32_t a = Bbuf + row * 128 + ((ch ^ (row & 7)) << 4);
                uint32_t b0, b1, b2, b3;
                LDSM_X4(b0, b1, b2, b3, a);
#pragma unroll
                for (int mt = 0; mt < 2; mt++) {
                    MMA16816(acc[mt][p*2],   afr[mt], b0, b1);
                    MMA16816(acc[mt][p*2+1], afr[mt], b2, b3);
                }
            }
        }
        __syncthreads();
    }

    int tensor = colBase >> 9;
    float alpha = (tensor == 0) ? 0.125f : 1.0f;
    __nv_bfloat16* dst = (tensor == 0) ? g_qc : (tensor == 1) ? g_kc : g_vc;

#pragma unroll
    for (int mt = 0; mt < 2; mt++)
#pragma unroll
        for (int nt = 0; nt < 8; nt++) {
            float* a4 = acc[mt][nt];
            int r0 = rowBase + wm + mt * 16 + (lane >> 2);
            int cc = (colBase & 511) + wn + nt * 8 + (lane & 3) * 2;
            int hh = cc >> 6, dd = cc & 63;
            int b = r0 >> 12, s = r0 & 4095;
            size_t off = ((size_t)((b << 3) + hh) * 4096 + s) * 64 + dd;
            *(uint32_t*)&dst[off] = pack_hi(a4[0]*alpha, a4[1]*alpha);
            *(uint32_t*)&dst[off + 8ULL*64] = pack_hi(a4[2]*alpha, a4[3]*alpha);
        }
}

// ---------------------------------------------------------------------------
// Fused Wo GEMM + dense-combine prologue + residual + bias + LayerNorm.
// CTA tile M=32 x N=512. A tile (32x512 bf16 = 32 KB) is STATIC smem:
//   mid CTAs cp.async it from g_xb; dense CTAs build it from split-K partials.
// smem: A 0..32K (16 chunks x 2 KB) | B0 32K | B1 64K |
//       lnS 98304 | lnQ 99328 | lnM 100352 | lnI 100480 | sinv 100608 (+1 KB)
// ---------------------------------------------------------------------------
#define WO_SMEM 101632

__device__ __forceinline__ void wo_ldB(const __nv_bfloat16* __restrict__ Bt,
                                       int k0, uint32_t Bbuf, int t)
{
#pragma unroll
    for (int it = 0; it < 8; it++) {
        int idx = it * 256 + t;
        int r = idx >> 2, c = idx & 3;
        CPASYNC16(Bbuf + r * 64 + ((c ^ ((r >> 1) & 3)) << 4),
                  &Bt[(size_t)r * 512 + k0 + c * 8]);
    }
    CPCOMMIT();
}

__global__ __launch_bounds__(256, 2)
void gemm_wo_ln(const __nv_bfloat16* __restrict__ A,
                const __nv_bfloat16* __restrict__ Bt,
                const float* __restrict__ X,
                const float* __restrict__ bo2,
                const float* __restrict__ gamma,
                const float* __restrict__ beta,
                float* __restrict__ out)
{
    extern __shared__ __align__(128) char sm[];
    uint32_t sb = smem_u32(sm);
    float* lnS  = (float*)(sm + 98304);   // [8][32]
    float* lnQ  = (float*)(sm + 99328);   // [8][32]
    float* lnM  = (float*)(sm + 100352);  // [32]
    float* lnI  = (float*)(sm + 100480);  // [32]
    float* sinv = (float*)(sm + 100608);  // [32][8]

    int t = threadIdx.x, w = t >> 5, lane = t & 31;
    int rowBase = blockIdx.x * 32;
    int b  = rowBase >> 12;
    int qb = (rowBase & 4095) >> 6;
    bool dense = (qb < 2) || (qb >= 62);

    // ---- prologue: fill A tile (16 chunks x [32 rows x 4 x 16B], swizzled) ----
    if (!dense) {
#pragma unroll
        for (int it = 0; it < 8; it++) {
            int u = it * 256 + t;                 // u = ch*128 + r*4 + c
            int ch = u >> 7, rc = u & 127;
            int r = rc >> 2, c = rc & 3;
            CPASYNC16(sb + ch * 2048 + r * 64 + ((c ^ ((r >> 1) & 3)) << 4),
                      &A[(size_t)(rowBase + r) * 512 + ch * 32 + c * 8]);
        }
        CPCOMMIT();            // group: A
        wo_ldB(Bt, 0, sb + 32768u, t);   // group: B0
    } else {
        int di = (qb < 2) ? qb : (qb - 60);
        // per-(row,head) 1/L
        {
            int r = t >> 3, h = t & 7;
            int rb = (rowBase & 63) + r;
            int g = ((b * 8 + h) * 4 + di);
            float L = 0.f;
#pragma unroll
            for (int s = 0; s < 8; s++) L += g_partl[(g * 8 + s) * 64 + rb];
            sinv[t] = 1.0f / L;
        }
        __syncthreads();
        wo_ldB(Bt, 0, sb + 32768u, t);   // group: B0 (start early)
        // combine partials directly into swizzled A smem
#pragma unroll
        for (int it = 0; it < 8; it++) {
            int u = it * 256 + t;
            int ch = u >> 7, rc = u & 127;
            int r = rc >> 2, c = rc & 3;
            int h = ch >> 1;
            int colh = (ch & 1) * 32 + c * 8;
            int rb = (rowBase & 63) + r;
            int g = ((b * 8 + h) * 4 + di);
            float o[8];
#pragma unroll
            for (int e = 0; e < 8; e++) o[e] = 0.f;
#pragma unroll
            for (int s = 0; s < 8; s++) {
                uint4 v = *(const uint4*)&g_partb[(size_t)(g * 8 + s) * 4096 + rb * 64 + colh];
                float2 a0 = unpk(v.x), a1 = unpk(v.y), a2 = unpk(v.z), a3 = unpk(v.w);
                o[0] += a0.x; o[1] += a0.y; o[2] += a1.x; o[3] += a1.y;
                o[4] += a2.x; o[5] += a2.y; o[6] += a3.x; o[7] += a3.y;
            }
            float inv = sinv[r * 8 + h];
            uint4 pk;
            pk.x = pack_hi(o[0] * inv, o[1] * inv);
            pk.y = pack_hi(o[2] * inv, o[3] * inv);
            pk.z = pack_hi(o[4] * inv, o[5] * inv);
            pk.w = pack_hi(o[6] * inv, o[7] * inv);
            *(uint4*)(sm + ch * 2048 + r * 64 + ((c ^ ((r >> 1) & 3)) << 4)) = pk;
        }
    }

    int laneA_row = (((lane >> 3) & 1) << 3) + (lane & 7);
    int laneA_ch  = (lane >> 4);
    int laneB_row = ((lane >> 4) << 3) + (lane & 7);
    int laneB_ch  = ((lane >> 3) & 1);

    float acc[2][8][4];
#pragma unroll
    for (int mt = 0; mt < 2; mt++)
#pragma unroll
        for (int nt = 0; nt < 8; nt++)
#pragma unroll
            for (int e = 0; e < 4; e++) acc[mt][nt][e] = 0.f;

    for (int i = 0; i < 16; i++) {
        int buf = i & 1;
        if (i < 15) {
            uint32_t Bbuf = sb + 32768u + (buf ? 0u : 32768u);
            wo_ldB(Bt, (i + 1) * 32, Bbuf, t);
            CPWAIT(1);
        } else {
            CPWAIT(0);
        }
        __syncthreads();

        uint32_t Ab = sb + (uint32_t)i * 2048u;
        uint32_t Bbuf = sb + 32768u + (buf ? 32768u : 0u);
#pragma unroll
        for (int ks = 0; ks < 2; ks++) {
            uint32_t afr[2][4];
#pragma unroll
            for (int mt = 0; mt < 2; mt++) {
                int row = mt * 16 + laneA_row;
                int ch  = ks * 2 + laneA_ch;
                LDSM_X4(afr[mt][0], afr[mt][1], afr[mt][2], afr[mt][3],
                        Ab + row * 64 + ((ch ^ ((row >> 1) & 3)) << 4));
            }
#pragma unroll
            for (int p = 0; p < 4; p++) {
                int row = w * 64 + p * 16 + laneB_row;
                int ch  = ks * 2 + laneB_ch;
                uint32_t b0, b1, b2, b3;
                LDSM_X4(b0, b1, b2, b3,
                        Bbuf + row * 64 + ((ch ^ ((row >> 1) & 3)) << 4));
#pragma unroll
                for (int mt = 0; mt < 2; mt++) {
                    MMA16816(acc[mt][p*2],   afr[mt], b0, b1);
                    MMA16816(acc[mt][p*2+1], afr[mt], b2, b3);
                }
            }
        }
        __syncthreads();
    }

    // ---- epilogue: h = acc + bo + x; LN stats; write out ----
    int rq = lane >> 2;
#pragma unroll
    for (int s = 0; s < 4; s++) {
        int mt = s >> 1, hi = (s & 1) * 2;
        int grow = rowBase + s * 8 + rq;
        float ssum = 0.f, qsum = 0.f;
#pragma unroll
        for (int nt = 0; nt < 8; nt++) {
            int col = w * 64 + nt * 8 + (lane & 3) * 2;
            float2 bv = *(const float2*)&bo2[col];
            float2 xv = *(const float2*)&X[(size_t)grow * 512 + col];
            float h0 = acc[mt][nt][hi]     + bv.x + xv.x;
            float h1 = acc[mt][nt][hi + 1] + bv.y + xv.y;
            acc[mt][nt][hi] = h0; acc[mt][nt][hi + 1] = h1;
            ssum += h0 + h1;
            qsum += h0 * h0 + h1 * h1;
        }
        ssum += __shfl_xor_sync(0xffffffffu, ssum, 1);
        ssum += __shfl_xor_sync(0xffffffffu, ssum, 2);
        qsum += __shfl_xor_sync(0xffffffffu, qsum, 1);
        qsum += __shfl_xor_sync(0xffffffffu, qsum, 2);
        if ((lane & 3) == 0) {
            lnS[w * 32 + s * 8 + rq] = ssum;
            lnQ[w * 32 + s * 8 + rq] = qsum;
        }
    }
    __syncthreads();
    if (t < 32) {
        float S = 0.f, Q = 0.f;
#pragma unroll
        for (int w8 = 0; w8 < 8; w8++) { S += lnS[w8 * 32 + t]; Q += lnQ[w8 * 32 + t]; }
        float mu  = S * (1.0f / 512.0f);
        float var = Q * (1.0f / 512.0f) - mu * mu;
        lnM[t] = mu;
        lnI[t] = rsqrtf(var + 1e-12f);
    }
    __syncthreads();

#pragma unroll
    for (int s = 0; s < 4; s++) {
        int mt = s >> 1, hi = (s & 1) * 2;
        int lrow = s * 8 + rq;
        float mu = lnM[lrow], inv = lnI[lrow];
        size_t grow = rowBase + lrow;
#pragma unroll
        for (int nt = 0; nt < 8; nt++) {
            int col = w * 64 + nt * 8 + (lane & 3) * 2;
            float2 gv = *(const float2*)&gamma[col];
            float2 bv = *(const float2*)&beta[col];
            float o0 = (acc[mt][nt][hi]     - mu) * inv * gv.x + bv.x;
            float o1 = (acc[mt][nt][hi + 1] - mu) * inv * gv.y + bv.y;
            *(float2*)&out[grow * 512 + col] = make_float2(o0, o1);
        }
    }
}

// ---------------------------------------------------------------------------
// HMMA attention (best-known config): 2-stage ring, hoisted Q, (256,2).
// ---------------------------------------------------------------------------
#define OFF_KS 8192
#define OFF_VS 24576
#define OFF_EX 40960
#define EX_PITCH 66
#define OFF_KM 57856
#define OFF_RL 58368
#define ATT_SMEM 58880

__device__ __forceinline__ int kb_of(bool mid, int qb, int chunk, int itk,
                                     const int* __restrict__ rand_blocks)
{
    if (!mid) return chunk * 8 + itk;
    if (itk < 3) return qb - 1 + itk;
    if (itk == 3) return 0;
    if (itk == 4) return 63;
    return rand_blocks[(qb - 2) * 3 + (itk - 5)];
}

__device__ __forceinline__ void attn_prefetch_kv(int bh, int kb, uint32_t KSb,
                                                 uint32_t VSb, int t)
{
    size_t koff = ((size_t)bh * 4096 + kb * 64) * 64;
#pragma unroll
    for (int it = 0; it < 2; it++) {
        int idx = it * 256 + t;
        int r = idx >> 3, c = idx & 7;
        CPASYNC16(KSb + r * 128 + ((c ^ (r & 7)) << 4), &g_kc[koff + r * 64 + c * 8]);
    }
#pragma unroll
    for (int it = 0; it < 2; it++) {
        int idx = it * 256 + t;
        int r = idx >> 3, c = idx & 7;
        CPASYNC16(VSb + r * 128 + ((c ^ (r & 7)) << 4), &g_vc[koff + r * 64 + c * 8]);
    }
    CPCOMMIT();
}

__global__ __launch_bounds__(256, 2)
void attn_hmma(const float* __restrict__ mask, const int* __restrict__ rand_blocks)
{
    extern __shared__ __align__(128) char sm[];
    uint32_t sb = smem_u32(sm);
    const uint32_t QS = sb;
    float* km   = (float*)(sm + OFF_KM);    // [2][64]
    float* redL = (float*)(sm + OFF_RL);
    float* ex   = (float*)(sm + OFF_EX);    // [64][EX_PITCH]

    int t = threadIdx.x, w = t >> 5, lane = t & 31;
    int wm = (w & 3) * 16;
    int wni = w >> 2;
    int wn  = wni * 32;

    int u  = blockIdx.x % 92;
    int bh = blockIdx.x / 92;
    int b  = bh >> 3, h = bh & 7;

    bool mid = (u < 60);
    int qb, chunk = 0, di = 0;
    if (mid) { qb = u + 2; }
    else {
        int d = u - 60;
        di = d >> 3; chunk = d & 7;
        qb = (di < 2) ? di : (60 + di);
    }

    // ---- prologue: Q + K0/V0 via cp.async (one group), km[0] ----
    {
        size_t qoff = ((size_t)bh * 4096 + qb * 64) * 64;
#pragma unroll
        for (int it = 0; it < 2; it++) {
            int idx = it * 256 + t;
            int r = idx >> 3, c = idx & 7;
            CPASYNC16(QS + r * 128 + ((c ^ (r & 7)) << 4), &g_qc[qoff + r * 64 + c * 8]);
        }
        int kb0 = kb_of(mid, qb, chunk, 0, rand_blocks);
        attn_prefetch_kv(bh, kb0, sb + OFF_KS, sb + OFF_VS, t);
        if (t < 64) km[t] = mask[b * 4096 + kb0 * 64 + t];
    }

    int r1 = wm + (lane >> 2), r2 = r1 + 8;
    float mq1 = mask[b * 4096 + qb * 64 + r1];
    float mq2 = mask[b * 4096 + qb * 64 + r2];

    float acc[8][4];
#pragma unroll
    for (int nn = 0; nn < 8; nn++)
#pragma unroll
        for (int e = 0; e < 4; e++) acc[nn][e] = 0.f;
    float ls1 = 0.f, ls2 = 0.f;

    int laneA_row = (((lane >> 3) & 1) << 3) + (lane & 7);
    int laneA_ch  = lane >> 4;
    int laneB_row = ((lane >> 4) << 3) + (lane & 7);
    int laneB_ch  = (lane >> 3) & 1;
    int laneV_row = lane & 15;
    int laneV_g   = lane >> 4;

    uint32_t qh[4][4];

    for (int itk = 0; itk < 8; itk++) {
        int buf = itk & 1;
        bool band = mid && (itk < 3);

        __syncthreads();
        if (itk < 7) {
            int kbn = kb_of(mid, qb, chunk, itk + 1, rand_blocks);
            attn_prefetch_kv(bh, kbn, sb + OFF_KS + (buf ^ 1) * 8192,
                             sb + OFF_VS + (buf ^ 1) * 8192, t);
            if (t < 64) km[(buf ^ 1) * 64 + t] = mask[b * 4096 + kbn * 64 + t];
            CPWAIT(1);
        } else {
            CPWAIT(0);
        }
        __syncthreads();

        if (itk == 0) {
            int row = wm + laneA_row;
#pragma unroll
            for (int ks = 0; ks < 4; ks++) {
                int ch = ks * 2 + laneA_ch;
                LDSM_X4(qh[ks][0], qh[ks][1], qh[ks][2], qh[ks][3],
                        QS + row * 128 + ((ch ^ (row & 7)) << 4));
            }
        }

        uint32_t KSb = sb + OFF_KS + buf * 8192;
        uint32_t VSb = sb + OFF_VS + buf * 8192;
        const float* kmask_s = km + buf * 64;

        // ---- QK ----
        float sc[4][4];
#pragma unroll
        for (int nt = 0; nt < 4; nt++)
#pragma unroll
            for (int e = 0; e < 4; e++) sc[nt][e] = 0.f;

#pragma unroll
        for (int ks = 0; ks < 4; ks++) {
            int kc2 = ks * 2;
#pragma unroll
            for (int g = 0; g < 2; g++) {
                uint32_t kh[4];
                int row = wn + g * 16 + laneB_row;
                int ch = kc2 + laneB_ch;
                LDSM_X4(kh[0], kh[1], kh[2], kh[3],
                        KSb + row * 128 + ((ch ^ (row & 7)) << 4));
                MMA16816(sc[g*2],   qh[ks], kh[0], kh[1]);
                MMA16816(sc[g*2+1], qh[ks], kh[2], kh[3]);
            }
        }

        // ---- mask ----
#pragma unroll
        for (int nt = 0; nt < 4; nt++) {
            int col = wn + nt * 8 + (lane & 3) * 2;
            float mk0 = kmask_s[col], mk1 = kmask_s[col + 1];
            float m00 = band ? mk0 * mq1 : mk0;
            float m01 = band ? mk1 * mq1 : mk1;
            float m10 = band ? mk0 * mq2 : mk0;
            float m11 = band ? mk1 * mq2 : mk1;
            sc[nt][0] += (1.0f - m00) * NEGF;
            sc[nt][1] += (1.0f - m01) * NEGF;
            sc[nt][2] += (1.0f - m10) * NEGF;
            sc[nt][3] += (1.0f - m11) * NEGF;
        }

        // ---- exp + bf16 pack ----
        uint32_t aph[2][4];
#pragma unroll
        for (int nt = 0; nt < 4; nt++) {
            float p00 = __expf(sc[nt][0]), p01 = __expf(sc[nt][1]);
            float p10 = __expf(sc[nt][2]), p11 = __expf(sc[nt][3]);
            ls1 += p00 + p01; ls2 += p10 + p11;
            int j = nt >> 1, hf = (nt & 1) * 2;
            aph[j][hf]     = pack_hi(p00, p01);
            aph[j][hf + 1] = pack_hi(p10, p11);
        }

        // ---- PV ----
#pragma unroll
        for (int j = 0; j < 2; j++) {
            int vrow = wn + j * 16 + laneV_row;
            uint32_t vbase = VSb + vrow * 128;
            int sw = (vrow & 7) << 4;
#pragma unroll
            for (int np = 0; np < 4; np++) {
                uint32_t vh4[4];
                int ch = np * 2 + laneV_g;
                LDSM_X4T(vh4[0], vh4[1], vh4[2], vh4[3], vbase + ((ch << 4) ^ sw));
                MMA16816(acc[np*2],   aph[j], vh4[0], vh4[1]);
                MMA16816(acc[np*2+1], aph[j], vh4[2], vh4[3]);
            }
        }
    }

    // ---- final ls combine ----
    ls1 += __shfl_xor_sync(0xffffffffu, ls1, 1);
    ls1 += __shfl_xor_sync(0xffffffffu, ls1, 2);
    ls2 += __shfl_xor_sync(0xffffffffu, ls2, 1);
    ls2 += __shfl_xor_sync(0xffffffffu, ls2, 2);
    if ((lane & 3) == 0) {
        redL[wni * 64 + r1] = ls1;
        redL[wni * 64 + r2] = ls2;
    }
    __syncthreads();
    ls1 = redL[r1] + redL[64 + r1];
    ls2 = redL[r2] + redL[64 + r2];

    // ---- cross-half acc reduction ----
    if (wni == 1) {
#pragma unroll
        for (int nn = 0; nn < 8; nn++) {
            int col = nn * 8 + (lane & 3) * 2;
            *(float2*)&ex[r1 * EX_PITCH + col] = make_float2(acc[nn][0], acc[nn][1]);
            *(float2*)&ex[r2 * EX_PITCH + col] = make_float2(acc[nn][2], acc[nn][3]);
        }
    }
    __syncthreads();
    if (wni == 0) {
#pragma unroll
        for (int nn = 0; nn < 8; nn++) {
            int col = nn * 8 + (lane & 3) * 2;
            float2 v1 = *(float2*)&ex[r1 * EX_PITCH + col];
            float2 v2 = *(float2*)&ex[r2 * EX_PITCH + col];
            acc[nn][0] += v1.x; acc[nn][1] += v1.y;
            acc[nn][2] += v2.x; acc[nn][3] += v2.y;
        }

        if (mid) {
            float inv1 = 1.0f / ls1, inv2 = 1.0f / ls2;
#pragma unroll
            for (int nn = 0; nn < 8; nn++) {
                int col = nn * 8 + (lane & 3) * 2;
                size_t o1 = ((size_t)(b * 4096 + qb * 64 + r1)) * 512 + h * 64 + col;
                size_t o2 = ((size_t)(b * 4096 + qb * 64 + r2)) * 512 + h * 64 + col;
                *(uint32_t*)&g_xb[o1] = pack_hi(acc[nn][0] * inv1, acc[nn][1] * inv1);
                *(uint32_t*)&g_xb[o2] = pack_hi(acc[nn][2] * inv2, acc[nn][3] * inv2);
            }
        } else {
            int slot = (bh * 4 + di) * 8 + chunk;
            __nv_bfloat16* pb = g_partb + (size_t)slot * 4096;
#pragma unroll
            for (int nn = 0; nn < 8; nn++) {
                int col = nn * 8 + (lane & 3) * 2;
                *(uint32_t*)&pb[r1 * 64 + col] = pack_hi(acc[nn][0], acc[nn][1]);
                *(uint32_t*)&pb[r2 * 64 + col] = pack_hi(acc[nn][2], acc[nn][3]);
            }
            if ((lane & 3) == 0) {
                g_partl[slot * 64 + r1] = ls1;
                g_partl[slot * 64 + r2] = ls2;
            }
        }
    }
}

// ---------------------------------------------------------------------------
extern "C" void kernel_launch(void* const* d_in, const int* in_sizes, int n_in,
                              void* d_out, int out_size)
{
    const float* x     = (const float*)d_in[0];
    const float* mask  = (const float*)d_in[1];
    const int*   rb    = (const int*)  d_in[2];
    const float* Wq    = (const float*)d_in[3];
    const float* Wk    = (const float*)d_in[4];
    const float* Wv    = (const float*)d_in[5];
    const float* Wo    = (const float*)d_in[6];
    const float* bo    = (const float*)d_in[7];
    const float* gamma = (const float*)d_in[8];
    const float* beta  = (const float*)d_in[9];
    float* out = (float*)d_out;

    __nv_bfloat16 *xb, *wtb;
    cudaGetSymbolAddress((void**)&xb, g_xb);
    cudaGetSymbolAddress((void**)&wtb, g_wtb);

    cudaFuncSetAttribute(gemm_wo_ln, cudaFuncAttributeMaxDynamicSharedMemorySize, WO_SMEM);
    cudaFuncSetAttribute(gemm_qkv,  cudaFuncAttributeMaxDynamicSharedMemorySize, GEMM_SMEM);
    cudaFuncSetAttribute(attn_hmma, cudaFuncAttributeMaxDynamicSharedMemorySize, ATT_SMEM);

    prep_kernel<<<4096 + 1024, 256>>>(x, xb, Wq, Wk, Wv, Wo, wtb);

    dim3 gq(12, 64);                         // 1536/128 x 8192/128
    gemm_qkv<<<gq, 256, GEMM_SMEM>>>(xb, wtb);

    attn_hmma<<<16 * 92, 256, ATT_SMEM>>>(mask, rb);

    gemm_wo_ln<<<256, 256, WO_SMEM>>>(xb, wtb + 3*262144, x, bo, gamma, beta, out);
}